// round 1
// baseline (speedup 1.0000x reference)
#include <cuda_runtime.h>

// Problem constants (fixed by setup_inputs)
#define BB   8
#define NN   4096
#define EE   16384
#define PP   64
#define DD   256
#define HH   512
#define MSGD 256
#define UPDD 254
#define STEPS 3

// Scratch (static device globals: allowed; no runtime allocation)
__device__ float g_ns [BB * NN * DD];            // mutable node states
__device__ float g_ein[(size_t)BB * EE * 2 * DD]; // edge MLP input  (B,E,512)
__device__ float g_he [(size_t)BB * EE * HH];     // edge hidden     (B,E,512)
__device__ float g_msg[(size_t)BB * EE * MSGD];   // messages        (B,E,256)
__device__ float g_inc[BB * NN * MSGD];           // incoming        (B,N,256)
__device__ float g_nin[BB * NN * (DD + MSGD)];    // node MLP input  (B,N,512)
__device__ float g_hn [BB * NN * HH];             // node hidden     (B,N,512)
__device__ float g_upd[BB * NN * UPDD];           // update          (B,N,254)

// ---------------------------------------------------------------------------
// Small glue kernels
// ---------------------------------------------------------------------------

__global__ void copy4_kernel(float4* __restrict__ dst, const float4* __restrict__ src, int n4) {
    int i = blockIdx.x * blockDim.x + threadIdx.x;
    if (i < n4) dst[i] = src[i];
}

__global__ void zero4_kernel(float4* __restrict__ dst, int n4) {
    int i = blockIdx.x * blockDim.x + threadIdx.x;
    if (i < n4) dst[i] = make_float4(0.f, 0.f, 0.f, 0.f);
}

// e_in[b,e,0:256] = ns[b,src[e],:]; e_in[b,e,256:512] = ns[b,snk[e],:]
__global__ void gather_edges_kernel(const float* __restrict__ ns,
                                    const int* __restrict__ src,
                                    const int* __restrict__ snk,
                                    float* __restrict__ ein) {
    const int per = DD / 4;  // 64 float4 per node row
    int idx = blockIdx.x * blockDim.x + threadIdx.x;
    if (idx >= BB * EE * per) return;
    int k4 = idx % per;
    int e  = (idx / per) % EE;
    int b  = idx / (per * EE);
    const float4* base = (const float4*)(ns + (size_t)b * NN * DD);
    float4* o = (float4*)(ein + ((size_t)b * EE + e) * (2 * DD));
    o[k4]       = base[(size_t)src[e] * per + k4];
    o[per + k4] = base[(size_t)snk[e] * per + k4];
}

// incoming[b, snk[e], :] += msgs[b, e, :]
__global__ void scatter_add_kernel(const float* __restrict__ msgs,
                                   const int* __restrict__ snk,
                                   float* __restrict__ inc) {
    int idx = blockIdx.x * blockDim.x + threadIdx.x;
    if (idx >= BB * EE * MSGD) return;
    int m = idx % MSGD;
    int e = (idx / MSGD) % EE;
    int b = idx / (MSGD * EE);
    atomicAdd(&inc[((size_t)b * NN + snk[e]) * MSGD + m], msgs[idx]);
}

// n_in[b,n,0:256] = incoming; n_in[b,n,256:512] = ns
__global__ void concat_nodes_kernel(const float* __restrict__ inc,
                                    const float* __restrict__ ns,
                                    float* __restrict__ nin) {
    const int per = DD / 4;  // 64
    int idx = blockIdx.x * blockDim.x + threadIdx.x;
    if (idx >= BB * NN * per) return;
    int k4 = idx % per;
    int n  = (idx / per) % NN;
    int b  = idx / (per * NN);
    size_t row = (size_t)b * NN + n;
    float4* o = (float4*)(nin + row * (DD + MSGD));
    o[k4]       = ((const float4*)(inc + row * MSGD))[k4];
    o[per + k4] = ((const float4*)(ns + row * DD))[k4];
}

// ns[b,n,2:256] += upd[b,n,:]
__global__ void add_update_kernel(const float* __restrict__ upd, float* __restrict__ ns) {
    int idx = blockIdx.x * blockDim.x + threadIdx.x;
    if (idx >= BB * NN * UPDD) return;
    int u = idx % UPDD;
    int n = (idx / UPDD) % NN;
    int b = idx / (UPDD * NN);
    ns[((size_t)b * NN + n) * DD + (DD - UPDD) + u] += upd[idx];
}

// ---------------------------------------------------------------------------
// Generic tiled fp32 GEMM: C[M,Nc] = act(A[M,K] @ W[K,Nc] + bias)
// 128x128 tile, BK=8, 256 threads, 8x8 per thread as 4 fragments of 4x4.
// Batched via blockIdx.z with element strides sa/sw/sc.
// ---------------------------------------------------------------------------
template <int RELU>
__global__ __launch_bounds__(256)
void gemm_tiled(const float* __restrict__ A, const float* __restrict__ W,
                const float* __restrict__ bias, float* __restrict__ C,
                int M, int K, int Nc, int useBias,
                long long sa, long long sw, long long sc) {
    A += (long long)blockIdx.z * sa;
    W += (long long)blockIdx.z * sw;
    C += (long long)blockIdx.z * sc;

    const int m0 = blockIdx.y * 128;
    const int n0 = blockIdx.x * 128;

    __shared__ __align__(16) float sA[8][128];
    __shared__ __align__(16) float sB[8][132];  // +4 pad

    const int tx = threadIdx.x & 15;   // 0..15 -> columns
    const int ty = threadIdx.x >> 4;   // 0..15 -> rows

    float acc[2][2][4][4];
#pragma unroll
    for (int p = 0; p < 2; p++)
#pragma unroll
        for (int q = 0; q < 2; q++)
#pragma unroll
            for (int i = 0; i < 4; i++)
#pragma unroll
                for (int j = 0; j < 4; j++) acc[p][q][i][j] = 0.f;

    const int arow = threadIdx.x >> 1;        // 0..127
    const int acol = (threadIdx.x & 1) * 4;   // 0 or 4
    const int bk   = threadIdx.x >> 5;        // 0..7
    const int bcol = (threadIdx.x & 31) * 4;  // 0..124

    for (int kt = 0; kt < K; kt += 8) {
        // Load A tile (float4; K is always a multiple of 4, rows guarded)
        {
            float4 v = make_float4(0.f, 0.f, 0.f, 0.f);
            if (m0 + arow < M)
                v = *(const float4*)(A + (size_t)(m0 + arow) * K + kt + acol);
            sA[acol + 0][arow] = v.x;
            sA[acol + 1][arow] = v.y;
            sA[acol + 2][arow] = v.z;
            sA[acol + 3][arow] = v.w;
        }
        // Load B tile (scalar, column-guarded: Nc=254 is neither aligned nor full)
        {
            const float* wr = W + (size_t)(kt + bk) * Nc;
#pragma unroll
            for (int j = 0; j < 4; j++) {
                int c = n0 + bcol + j;
                sB[bk][bcol + j] = (c < Nc) ? wr[c] : 0.f;
            }
        }
        __syncthreads();

#pragma unroll
        for (int kk = 0; kk < 8; kk++) {
            float a0[4], a1[4], b0[4], b1[4];
            *(float4*)a0 = *(const float4*)&sA[kk][ty * 4];
            *(float4*)a1 = *(const float4*)&sA[kk][64 + ty * 4];
            *(float4*)b0 = *(const float4*)&sB[kk][tx * 4];
            *(float4*)b1 = *(const float4*)&sB[kk][64 + tx * 4];
#pragma unroll
            for (int i = 0; i < 4; i++)
#pragma unroll
                for (int j = 0; j < 4; j++) {
                    acc[0][0][i][j] += a0[i] * b0[j];
                    acc[0][1][i][j] += a0[i] * b1[j];
                    acc[1][0][i][j] += a1[i] * b0[j];
                    acc[1][1][i][j] += a1[i] * b1[j];
                }
        }
        __syncthreads();
    }

    // Epilogue: bias + optional ReLU, bounds-guarded
#pragma unroll
    for (int p = 0; p < 2; p++)
#pragma unroll
        for (int i = 0; i < 4; i++) {
            int r = m0 + p * 64 + ty * 4 + i;
            if (r >= M) continue;
#pragma unroll
            for (int q = 0; q < 2; q++)
#pragma unroll
                for (int j = 0; j < 4; j++) {
                    int c = n0 + q * 64 + tx * 4 + j;
                    if (c >= Nc) continue;
                    float v = acc[p][q][i][j];
                    if (useBias) v += bias[c];
                    if (RELU) v = fmaxf(v, 0.f);
                    C[(size_t)r * Nc + c] = v;
                }
        }
}

// ---------------------------------------------------------------------------
// Launcher
// ---------------------------------------------------------------------------
extern "C" void kernel_launch(void* const* d_in, const int* in_sizes, int n_in,
                              void* d_out, int out_size) {
    (void)in_sizes; (void)n_in; (void)out_size;

    const float* nodes = (const float*)d_in[0];
    const float* attn  = (const float*)d_in[1];
    const float* We1   = (const float*)d_in[2];
    const float* be1   = (const float*)d_in[3];
    const float* We2   = (const float*)d_in[4];
    const float* be2   = (const float*)d_in[5];
    const float* Wn1   = (const float*)d_in[6];
    const float* bn1   = (const float*)d_in[7];
    const float* Wn2   = (const float*)d_in[8];
    const float* bn2   = (const float*)d_in[9];
    const int*   esrc  = (const int*)d_in[10];
    const int*   esnk  = (const int*)d_in[11];
    float*       out   = (float*)d_out;

    float *ns, *ein, *he, *msg, *inc, *nin, *hn, *upd;
    cudaGetSymbolAddress((void**)&ns,  g_ns);
    cudaGetSymbolAddress((void**)&ein, g_ein);
    cudaGetSymbolAddress((void**)&he,  g_he);
    cudaGetSymbolAddress((void**)&msg, g_msg);
    cudaGetSymbolAddress((void**)&inc, g_inc);
    cudaGetSymbolAddress((void**)&nin, g_nin);
    cudaGetSymbolAddress((void**)&hn,  g_hn);
    cudaGetSymbolAddress((void**)&upd, g_upd);

    const int T = 256;

    // ns = nodes_states (copy into mutable scratch)
    {
        int n4 = BB * NN * DD / 4;
        copy4_kernel<<<(n4 + T - 1) / T, T>>>((float4*)ns, (const float4*)nodes, n4);
    }

    const int ME = BB * EE;   // 131072 edge rows
    const int MN = BB * NN;   // 32768 node rows

    for (int step = 0; step < STEPS; step++) {
        // 1) gather + concat edge inputs
        {
            int n = BB * EE * (DD / 4);
            gather_edges_kernel<<<(n + T - 1) / T, T>>>(ns, esrc, esnk, ein);
        }
        // 2) h = relu(e_in @ W_e1 + b_e1)   (131072 x 512 x 512)
        gemm_tiled<1><<<dim3(HH / 128, ME / 128, 1), T>>>(
            ein, We1, be1, he, ME, 2 * DD, HH, 1, 0, 0, 0);
        // 3) msgs = h @ W_e2 + b_e2         (131072 x 512 x 256)
        gemm_tiled<0><<<dim3(MSGD / 128, ME / 128, 1), T>>>(
            he, We2, be2, msg, ME, HH, MSGD, 1, 0, 0, 0);
        // 4) incoming = scatter_add(msgs, sinks)
        {
            int n4 = BB * NN * MSGD / 4;
            zero4_kernel<<<(n4 + T - 1) / T, T>>>((float4*)inc, n4);
            int n = BB * EE * MSGD;
            scatter_add_kernel<<<(n + T - 1) / T, T>>>(msg, esnk, inc);
        }
        // 5) n_in = [incoming, ns]
        {
            int n = BB * NN * (DD / 4);
            concat_nodes_kernel<<<(n + T - 1) / T, T>>>(inc, ns, nin);
        }
        // 6) h2 = relu(n_in @ W_n1 + b_n1)  (32768 x 512 x 512)
        gemm_tiled<1><<<dim3(HH / 128, MN / 128, 1), T>>>(
            nin, Wn1, bn1, hn, MN, DD + MSGD, HH, 1, 0, 0, 0);
        // 7) upd = h2 @ W_n2 + b_n2         (32768 x 512 x 254)
        gemm_tiled<0><<<dim3((UPDD + 127) / 128, MN / 128, 1), T>>>(
            hn, Wn2, bn2, upd, MN, HH, UPDD, 1, 0, 0, 0);
        // 8) ns[..., 2:] += upd
        {
            int n = BB * NN * UPDD;
            add_update_kernel<<<(n + T - 1) / T, T>>>(upd, ns);
        }
    }

    // extraction: out[b,p,d] = sum_n attn[b,p,n] * ns[b,n,d]   (batched GEMM)
    gemm_tiled<0><<<dim3(DD / 128, 1, BB), T>>>(
        attn, ns, nullptr, out, PP, NN, DD, 0,
        (long long)PP * NN, (long long)NN * DD, (long long)PP * DD);
}

// round 4
// speedup vs baseline: 5.0285x; 5.0285x over previous
#include <cuda_runtime.h>
#include <cstdint>

// Problem constants
#define BB   8
#define NN   4096
#define EE   16384
#define PP   64
#define DD   256
#define HH   512
#define MSGD 256
#define UPDD 254
#define STEPS 3
#define KDIM 512

// Tiling
#define TMv 128
#define TNv 128
#define BKv 32
#define NCHUNK (KDIM / BKv)        // 16
#define ASTR 36                    // padded row stride in floats (bank-conflict-free)
#define ABYTES (TMv * ASTR * 4)    // 18432
#define BBYTES (TNv * ASTR * 4)    // 18432
#define BUFBYTES (ABYTES + BBYTES) // 36864
#define SOFF_SRC (2 * BUFBYTES)          // 73728
#define SOFF_SNK (SOFF_SRC + 512)
#define SMEM_BYTES (SOFF_SNK + 512)      // 74752

// ---------------------------------------------------------------------------
// Scratch (static device globals — no runtime allocation)
// ---------------------------------------------------------------------------
__device__ float g_ns [BB * NN * DD];
__device__ float g_he [(size_t)BB * EE * HH];
__device__ float g_inc[BB * NN * MSGD];
__device__ float g_hn [BB * NN * HH];
__device__ float g_wte1[HH   * KDIM];
__device__ float g_wte2[MSGD * KDIM];
__device__ float g_wtn1[HH   * KDIM];
__device__ float g_wtn2[UPDD * KDIM];

// ---------------------------------------------------------------------------
// Helpers (portable PTX only: cp.async + mma.sync tf32)
// ---------------------------------------------------------------------------
__device__ __forceinline__ uint32_t smem_u32(const void* p) {
    uint32_t a;
    asm("{ .reg .u64 t; cvta.to.shared.u64 t, %1; cvt.u32.u64 %0, t; }" : "=r"(a) : "l"(p));
    return a;
}
__device__ __forceinline__ void cp16(uint32_t dst, const void* src, uint32_t sz) {
    asm volatile("cp.async.ca.shared.global [%0], [%1], 16, %2;\n" :: "r"(dst), "l"(src), "r"(sz));
}
#define CP_COMMIT() asm volatile("cp.async.commit_group;\n" ::: "memory")

__device__ __forceinline__ uint32_t f2tf32(float f) {
    uint32_t u;
    asm("cvt.rna.tf32.f32 %0, %1;" : "=r"(u) : "f"(f));
    return u;
}
__device__ __forceinline__ float tf32r(float f) {  // round fp32 -> tf32 value (as float)
    return __uint_as_float(f2tf32(f));
}
__device__ __forceinline__ void mma1688(float* c, const uint32_t* a, const uint32_t* b) {
    asm volatile(
        "mma.sync.aligned.m16n8k8.row.col.f32.tf32.tf32.f32 "
        "{%0,%1,%2,%3}, {%4,%5,%6,%7}, {%8,%9}, {%0,%1,%2,%3};"
        : "+f"(c[0]), "+f"(c[1]), "+f"(c[2]), "+f"(c[3])
        : "r"(a[0]), "r"(a[1]), "r"(a[2]), "r"(a[3]), "r"(b[0]), "r"(b[1]));
}

// ---------------------------------------------------------------------------
// Tensor-core tf32 GEMM (mma.sync), fused A-sources and fused epilogues.
// AMODE: 0 = direct A[m,k]
//        1 = edge gather: k in [0,256) from ns[src[e]], [256,512) from ns[snk[e]]
//        2 = node concat: k in [0,256) from inc[m],     [256,512) from ns[m]
// EPI:   0 = C[m,c] = (relu?)(v + bias)
//        1 = atomicAdd(inc[b, snk[e], c], v + bias)
//        2 = ns[m, 2+c] += v + bias   (c < 254)
// C layout 128x128 per CTA; 8 warps: wm = wid&3 (32 rows), wn = wid>>2 (64 cols)
// ---------------------------------------------------------------------------
template <int AMODE>
__device__ __forceinline__ void load_chunk(
    int c, uint32_t sb, int tid, int m0, int n0, int bIdx,
    const float* __restrict__ A, const float* __restrict__ Wt,
    const float* __restrict__ nsrc, const float* __restrict__ incsrc,
    const int* sSrc, const int* sSnk, int Ncol) {
    const int kt = c * BKv;
    const uint32_t abuf = sb + (uint32_t)(c & 1) * BUFBYTES;
    const uint32_t bbuf = abuf + ABYTES;
    // A tile: 128 rows x 32 floats, padded rows of 144B
#pragma unroll
    for (int j = 0; j < 4; j++) {
        int idx = tid + 256 * j;      // 0..1023
        int row = idx >> 3, c4 = idx & 7;
        uint32_t dst = abuf + (uint32_t)(row * 144 + c4 * 16);
        const float* src;
        if (AMODE == 0) {
            src = A + (size_t)(m0 + row) * KDIM + kt + c4 * 4;
        } else if (AMODE == 1) {
            int node = (kt < DD) ? sSrc[row] : sSnk[row];
            int cb = (kt < DD) ? kt : (kt - DD);
            src = nsrc + ((size_t)bIdx * NN + node) * DD + cb + c4 * 4;
        } else {
            size_t rg = (size_t)(m0 + row);
            src = (kt < DD) ? (incsrc + rg * DD + kt + c4 * 4)
                            : (nsrc + rg * DD + (kt - DD) + c4 * 4);
        }
        cp16(dst, src, 16);
    }
    // B tile: 128 n-rows x 32 floats of W^T, row-guarded (Ncol=254 case)
#pragma unroll
    for (int j = 0; j < 4; j++) {
        int idx = tid + 256 * j;
        int row = idx >> 3, c4 = idx & 7;
        uint32_t dst = bbuf + (uint32_t)(row * 144 + c4 * 16);
        int nr = n0 + row;
        int ok = nr < Ncol;
        cp16(dst, Wt + (size_t)(ok ? nr : 0) * KDIM + kt + c4 * 4, ok ? 16u : 0u);
    }
    CP_COMMIT();
}

template <int AMODE, int EPI, int RELU>
__global__ __launch_bounds__(256)
void gemm_mma(const float* __restrict__ A, const float* __restrict__ Wt,
              const float* __restrict__ bias, float* __restrict__ C,
              const int* __restrict__ esrc, const int* __restrict__ esnk,
              const float* __restrict__ nsrc, const float* __restrict__ incsrc,
              float* __restrict__ nsdst, int M, int Ncol) {
    extern __shared__ __align__(16) char smem[];
    const uint32_t sb = smem_u32(smem);
    const int tid = threadIdx.x;
    const int wid = tid >> 5, lane = tid & 31;
    const int g = lane >> 2, t4 = lane & 3;
    const int wm = wid & 3, wn = wid >> 2;
    const int m0 = blockIdx.y * TMv;
    const int n0 = blockIdx.x * TNv;
    const int bIdx = (AMODE == 1 || EPI == 1) ? (m0 / EE) : 0;
    int* sSrc = (int*)(smem + SOFF_SRC);
    int* sSnk = (int*)(smem + SOFF_SNK);

    if (AMODE == 1 || EPI == 1) {
        if (tid < TMv) {
            int e = (m0 - bIdx * EE) + tid;
            if (AMODE == 1) sSrc[tid] = esrc[e];
            sSnk[tid] = esnk[e];
        }
        __syncthreads();
    }

    float acc[2][8][4];
#pragma unroll
    for (int mt = 0; mt < 2; mt++)
#pragma unroll
        for (int nt = 0; nt < 8; nt++)
#pragma unroll
            for (int i = 0; i < 4; i++) acc[mt][nt][i] = 0.f;

    load_chunk<AMODE>(0, sb, tid, m0, n0, bIdx, A, Wt, nsrc, incsrc, sSrc, sSnk, Ncol);
    load_chunk<AMODE>(1, sb, tid, m0, n0, bIdx, A, Wt, nsrc, incsrc, sSrc, sSnk, Ncol);

#pragma unroll 1
    for (int c = 0; c < NCHUNK; c++) {
        if (c < NCHUNK - 1) asm volatile("cp.async.wait_group 1;" ::: "memory");
        else                asm volatile("cp.async.wait_group 0;" ::: "memory");
        __syncthreads();

        const float* sAf = (const float*)(smem + (size_t)(c & 1) * BUFBYTES);
        const float* sBf = sAf + TMv * ASTR;
#pragma unroll
        for (int kk = 0; kk < 4; kk++) {
            const int k8 = kk * 8;
            uint32_t a[2][4], b[8][2];
#pragma unroll
            for (int mt = 0; mt < 2; mt++) {
                int r0 = wm * 32 + mt * 16 + g;
                a[mt][0] = f2tf32(sAf[r0 * ASTR + k8 + t4]);
                a[mt][1] = f2tf32(sAf[(r0 + 8) * ASTR + k8 + t4]);
                a[mt][2] = f2tf32(sAf[r0 * ASTR + k8 + 4 + t4]);
                a[mt][3] = f2tf32(sAf[(r0 + 8) * ASTR + k8 + 4 + t4]);
            }
#pragma unroll
            for (int nt = 0; nt < 8; nt++) {
                int col = wn * 64 + nt * 8 + g;
                b[nt][0] = __float_as_uint(sBf[col * ASTR + k8 + t4]);      // weights pre-rounded
                b[nt][1] = __float_as_uint(sBf[col * ASTR + k8 + 4 + t4]);
            }
#pragma unroll
            for (int mt = 0; mt < 2; mt++)
#pragma unroll
                for (int nt = 0; nt < 8; nt++) mma1688(acc[mt][nt], a[mt], b[nt]);
        }
        __syncthreads();
        if (c + 2 < NCHUNK)
            load_chunk<AMODE>(c + 2, sb, tid, m0, n0, bIdx, A, Wt, nsrc, incsrc, sSrc, sSnk, Ncol);
    }

    // Epilogue. Thread holds C rows {r, r+8} x cols {cc, cc+1} per (mt, nt).
#pragma unroll
    for (int mt = 0; mt < 2; mt++) {
        const int rl0 = wm * 32 + mt * 16 + g;      // CTA-local rows rl0, rl0+8
#pragma unroll
        for (int nt = 0; nt < 8; nt++) {
            const int cc = n0 + wn * 64 + nt * 8 + t4 * 2;
            float v0 = acc[mt][nt][0] + bias[cc];
            float v1 = acc[mt][nt][1] + bias[cc + 1];
            float v2 = acc[mt][nt][2] + bias[cc];
            float v3 = acc[mt][nt][3] + bias[cc + 1];
            if (RELU) {
                v0 = fmaxf(v0, 0.f); v1 = fmaxf(v1, 0.f);
                v2 = fmaxf(v2, 0.f); v3 = fmaxf(v3, 0.f);
            }
            if (EPI == 0) {
                float* p0 = C + (size_t)(m0 + rl0) * Ncol + cc;
                float* p1 = C + (size_t)(m0 + rl0 + 8) * Ncol + cc;
                p0[0] = v0; p0[1] = v1;
                p1[0] = v2; p1[1] = v3;
            } else if (EPI == 1) {
                float* d0 = C + ((size_t)bIdx * NN + sSnk[rl0]) * MSGD + cc;
                float* d1 = C + ((size_t)bIdx * NN + sSnk[rl0 + 8]) * MSGD + cc;
                atomicAdd(d0, v0); atomicAdd(d0 + 1, v1);
                atomicAdd(d1, v2); atomicAdd(d1 + 1, v3);
            } else {
                float* d0 = nsdst + (size_t)(m0 + rl0) * DD + (DD - UPDD);
                float* d1 = nsdst + (size_t)(m0 + rl0 + 8) * DD + (DD - UPDD);
                if (cc < UPDD)     { d0[cc] += v0;     d1[cc] += v2; }
                if (cc + 1 < UPDD) { d0[cc + 1] += v1; d1[cc + 1] += v3; }
            }
        }
    }
}

// ---------------------------------------------------------------------------
// Glue kernels
// ---------------------------------------------------------------------------
__global__ void copy4_kernel(float4* __restrict__ dst, const float4* __restrict__ src, int n4) {
    int i = blockIdx.x * blockDim.x + threadIdx.x;
    if (i < n4) dst[i] = src[i];
}
__global__ void zero4_kernel(float4* __restrict__ dst, int n4) {
    int i = blockIdx.x * blockDim.x + threadIdx.x;
    if (i < n4) dst[i] = make_float4(0.f, 0.f, 0.f, 0.f);
}
// out[n*K+k] = tf32_round(in[k*N+n])
__global__ void transpose_kernel(const float* __restrict__ in, float* __restrict__ out,
                                 int K, int N) {
    __shared__ float t[32][33];
    int k0 = blockIdx.y * 32, n0 = blockIdx.x * 32;
    int tx = threadIdx.x, ty = threadIdx.y;
    for (int i = ty; i < 32; i += 8) {
        int k = k0 + i, n = n0 + tx;
        t[i][tx] = (k < K && n < N) ? in[(size_t)k * N + n] : 0.f;
    }
    __syncthreads();
    for (int i = ty; i < 32; i += 8) {
        int n = n0 + i, k = k0 + tx;
        if (n < N && k < K) out[(size_t)n * K + k] = tf32r(t[tx][i]);
    }
}

// SIMT fp32 GEMM for the small extraction einsum (batched)
template <int RELU>
__global__ __launch_bounds__(256)
void gemm_tiled(const float* __restrict__ A, const float* __restrict__ W,
                const float* __restrict__ bias, float* __restrict__ C,
                int M, int K, int Nc, int useBias,
                long long sa, long long sw, long long sc) {
    A += (long long)blockIdx.z * sa;
    W += (long long)blockIdx.z * sw;
    C += (long long)blockIdx.z * sc;
    const int m0 = blockIdx.y * 128, n0 = blockIdx.x * 128;
    __shared__ __align__(16) float sA[8][128];
    __shared__ __align__(16) float sB[8][132];
    const int tx = threadIdx.x & 15, ty = threadIdx.x >> 4;
    float acc[2][2][4][4];
#pragma unroll
    for (int p = 0; p < 2; p++)
#pragma unroll
        for (int q = 0; q < 2; q++)
#pragma unroll
            for (int i = 0; i < 4; i++)
#pragma unroll
                for (int j = 0; j < 4; j++) acc[p][q][i][j] = 0.f;
    const int arow = threadIdx.x >> 1, acol = (threadIdx.x & 1) * 4;
    const int bk = threadIdx.x >> 5, bcol = (threadIdx.x & 31) * 4;
    for (int kt = 0; kt < K; kt += 8) {
        float4 v = make_float4(0.f, 0.f, 0.f, 0.f);
        if (m0 + arow < M) v = *(const float4*)(A + (size_t)(m0 + arow) * K + kt + acol);
        sA[acol + 0][arow] = v.x; sA[acol + 1][arow] = v.y;
        sA[acol + 2][arow] = v.z; sA[acol + 3][arow] = v.w;
        const float* wr = W + (size_t)(kt + bk) * Nc;
#pragma unroll
        for (int j = 0; j < 4; j++) {
            int c = n0 + bcol + j;
            sB[bk][bcol + j] = (c < Nc) ? wr[c] : 0.f;
        }
        __syncthreads();
#pragma unroll
        for (int kk = 0; kk < 8; kk++) {
            float a0[4], a1[4], b0[4], b1[4];
            *(float4*)a0 = *(const float4*)&sA[kk][ty * 4];
            *(float4*)a1 = *(const float4*)&sA[kk][64 + ty * 4];
            *(float4*)b0 = *(const float4*)&sB[kk][tx * 4];
            *(float4*)b1 = *(const float4*)&sB[kk][64 + tx * 4];
#pragma unroll
            for (int i = 0; i < 4; i++)
#pragma unroll
                for (int j = 0; j < 4; j++) {
                    acc[0][0][i][j] += a0[i] * b0[j];
                    acc[0][1][i][j] += a0[i] * b1[j];
                    acc[1][0][i][j] += a1[i] * b0[j];
                    acc[1][1][i][j] += a1[i] * b1[j];
                }
        }
        __syncthreads();
    }
#pragma unroll
    for (int p = 0; p < 2; p++)
#pragma unroll
        for (int i = 0; i < 4; i++) {
            int r = m0 + p * 64 + ty * 4 + i;
            if (r >= M) continue;
#pragma unroll
            for (int q = 0; q < 2; q++)
#pragma unroll
                for (int j = 0; j < 4; j++) {
                    int c = n0 + q * 64 + tx * 4 + j;
                    if (c >= Nc) continue;
                    float v = acc[p][q][i][j];
                    if (useBias) v += bias[c];
                    if (RELU) v = fmaxf(v, 0.f);
                    C[(size_t)r * Nc + c] = v;
                }
        }
}

// ---------------------------------------------------------------------------
// Launcher
// ---------------------------------------------------------------------------
extern "C" void kernel_launch(void* const* d_in, const int* in_sizes, int n_in,
                              void* d_out, int out_size) {
    (void)in_sizes; (void)n_in; (void)out_size;
    const float* nodes = (const float*)d_in[0];
    const float* attn  = (const float*)d_in[1];
    const float* We1   = (const float*)d_in[2];
    const float* be1   = (const float*)d_in[3];
    const float* We2   = (const float*)d_in[4];
    const float* be2   = (const float*)d_in[5];
    const float* Wn1   = (const float*)d_in[6];
    const float* bn1   = (const float*)d_in[7];
    const float* Wn2   = (const float*)d_in[8];
    const float* bn2   = (const float*)d_in[9];
    const int*   esrc  = (const int*)d_in[10];
    const int*   esnk  = (const int*)d_in[11];
    float*       out   = (float*)d_out;

    float *ns, *he, *inc, *hn, *wte1, *wte2, *wtn1, *wtn2;
    cudaGetSymbolAddress((void**)&ns,   g_ns);
    cudaGetSymbolAddress((void**)&he,   g_he);
    cudaGetSymbolAddress((void**)&inc,  g_inc);
    cudaGetSymbolAddress((void**)&hn,   g_hn);
    cudaGetSymbolAddress((void**)&wte1, g_wte1);
    cudaGetSymbolAddress((void**)&wte2, g_wte2);
    cudaGetSymbolAddress((void**)&wtn1, g_wtn1);
    cudaGetSymbolAddress((void**)&wtn2, g_wtn2);

    cudaFuncSetAttribute(gemm_mma<1, 0, 1>, cudaFuncAttributeMaxDynamicSharedMemorySize, SMEM_BYTES);
    cudaFuncSetAttribute(gemm_mma<0, 1, 0>, cudaFuncAttributeMaxDynamicSharedMemorySize, SMEM_BYTES);
    cudaFuncSetAttribute(gemm_mma<2, 0, 1>, cudaFuncAttributeMaxDynamicSharedMemorySize, SMEM_BYTES);
    cudaFuncSetAttribute(gemm_mma<0, 2, 0>, cudaFuncAttributeMaxDynamicSharedMemorySize, SMEM_BYTES);

    const int T = 256;
    // Pre-transpose weights to [N,K] K-major, rounded to tf32
    transpose_kernel<<<dim3(HH / 32, KDIM / 32), dim3(32, 8)>>>(We1, wte1, KDIM, HH);
    transpose_kernel<<<dim3(MSGD / 32, KDIM / 32), dim3(32, 8)>>>(We2, wte2, HH, MSGD);
    transpose_kernel<<<dim3(HH / 32, KDIM / 32), dim3(32, 8)>>>(Wn1, wtn1, KDIM, HH);
    transpose_kernel<<<dim3((UPDD + 31) / 32, KDIM / 32), dim3(32, 8)>>>(Wn2, wtn2, HH, UPDD);
    // ns = nodes_states
    {
        int n4 = BB * NN * DD / 4;
        copy4_kernel<<<(n4 + T - 1) / T, T>>>((float4*)ns, (const float4*)nodes, n4);
    }

    const int ME = BB * EE;  // 131072
    const int MN = BB * NN;  // 32768

    for (int step = 0; step < STEPS; step++) {
        {
            int n4 = BB * NN * MSGD / 4;
            zero4_kernel<<<(n4 + T - 1) / T, T>>>((float4*)inc, n4);
        }
        // GEMM1: he = relu(gather(ns) @ W_e1 + b_e1)   [131072 x 512 x 512]
        gemm_mma<1, 0, 1><<<dim3(HH / TNv, ME / TMv), 256, SMEM_BYTES>>>(
            nullptr, wte1, be1, he, esrc, esnk, ns, nullptr, nullptr, ME, HH);
        // GEMM2: inc[snk] += he @ W_e2 + b_e2          [131072 x 512 x 256]
        gemm_mma<0, 1, 0><<<dim3(MSGD / TNv, ME / TMv), 256, SMEM_BYTES>>>(
            he, wte2, be2, inc, esrc, esnk, nullptr, nullptr, nullptr, ME, MSGD);
        // GEMM3: hn = relu(concat(inc, ns) @ W_n1 + b_n1)  [32768 x 512 x 512]
        gemm_mma<2, 0, 1><<<dim3(HH / TNv, MN / TMv), 256, SMEM_BYTES>>>(
            nullptr, wtn1, bn1, hn, nullptr, nullptr, ns, inc, nullptr, MN, HH);
        // GEMM4: ns[:, 2:] += hn @ W_n2 + b_n2         [32768 x 512 x 254]
        gemm_mma<0, 2, 0><<<dim3(2, MN / TMv), 256, SMEM_BYTES>>>(
            hn, wtn2, bn2, nullptr, nullptr, nullptr, nullptr, nullptr, ns, MN, UPDD);
    }

    // extraction (fp32 SIMT): out[b,p,d] = sum_n attn[b,p,n] * ns[b,n,d]
    gemm_tiled<0><<<dim3(DD / 128, 1, BB), 256>>>(
        attn, ns, nullptr, out, PP, NN, DD, 0,
        (long long)PP * NN, (long long)NN * DD, (long long)PP * DD);
}

// round 5
// speedup vs baseline: 6.2861x; 1.2501x over previous
#include <cuda_runtime.h>
#include <cstdint>

// Problem constants
#define BB   8
#define NN   4096
#define EE   16384
#define PP   64
#define DD   256
#define HH   512
#define MSGD 256
#define UPDD 254
#define STEPS 3
#define KDIM 512

// Tiling: CTA 128x256, 8 warps (2 row x 4 col), warp tile 64x64, BK=32
#define TMv 128
#define TNv 256
#define BKv 32
#define NCHUNK (KDIM / BKv)          // 16
#define ABYTES_ (TMv * 128)          // 16384 (128B per row of 32 floats)
#define BBYTES_ (TNv * 128)          // 32768
#define BUFBYTES (ABYTES_ + BBYTES_) // 49152
#define SOFF_SRC (2 * BUFBYTES)      // 98304
#define SOFF_SNK (SOFF_SRC + 512)
#define SMEM_BYTES (SOFF_SNK + 512)  // 99328

// ---------------------------------------------------------------------------
// Scratch (static device globals — no runtime allocation)
// ---------------------------------------------------------------------------
__device__ float g_ns   [BB * NN * DD];
__device__ float g_nstf [BB * NN * DD];
__device__ float g_he   [(size_t)BB * EE * HH];
__device__ float g_inc  [BB * NN * MSGD];
__device__ float g_inctf[BB * NN * MSGD];
__device__ float g_hn   [BB * NN * HH];
__device__ float g_wte1[HH   * KDIM];
__device__ float g_wte2[MSGD * KDIM];
__device__ float g_wtn1[HH   * KDIM];
__device__ float g_wtn2[UPDD * KDIM];

// ---------------------------------------------------------------------------
// Helpers (portable PTX only: cp.async + ldmatrix + mma.sync tf32)
// ---------------------------------------------------------------------------
__device__ __forceinline__ uint32_t smem_u32(const void* p) {
    uint32_t a;
    asm("{ .reg .u64 t; cvta.to.shared.u64 t, %1; cvt.u32.u64 %0, t; }" : "=r"(a) : "l"(p));
    return a;
}
__device__ __forceinline__ void cp16(uint32_t dst, const void* src, uint32_t sz) {
    asm volatile("cp.async.ca.shared.global [%0], [%1], 16, %2;\n" :: "r"(dst), "l"(src), "r"(sz));
}
#define CP_COMMIT() asm volatile("cp.async.commit_group;\n" ::: "memory")

__device__ __forceinline__ uint32_t f2tf32(float f) {
    uint32_t u;
    asm("cvt.rna.tf32.f32 %0, %1;" : "=r"(u) : "f"(f));
    return u;
}
__device__ __forceinline__ float tf32r(float f) { return __uint_as_float(f2tf32(f)); }

__device__ __forceinline__ void mma1688(float* c, const uint32_t* a, const uint32_t* b) {
    asm volatile(
        "mma.sync.aligned.m16n8k8.row.col.f32.tf32.tf32.f32 "
        "{%0,%1,%2,%3}, {%4,%5,%6,%7}, {%8,%9}, {%0,%1,%2,%3};"
        : "+f"(c[0]), "+f"(c[1]), "+f"(c[2]), "+f"(c[3])
        : "r"(a[0]), "r"(a[1]), "r"(a[2]), "r"(a[3]), "r"(b[0]), "r"(b[1]));
}
#define LDSM4(r0, r1, r2, r3, a) \
    asm volatile("ldmatrix.sync.aligned.m8n8.x4.shared.b16 {%0,%1,%2,%3}, [%4];" \
        : "=r"(r0), "=r"(r1), "=r"(r2), "=r"(r3) : "r"(a))

// ---------------------------------------------------------------------------
// tf32 mma.sync GEMM with fused A-sources and fused epilogues.
// AMODE: 0 = direct A[m,k] (pre-rounded tf32)
//        1 = edge gather from ns_tf: k<256 -> src[e], k>=256 -> snk[e]
//        2 = node concat: k<256 -> inc_tf[m], k>=256 -> ns_tf[m]
// EPI:   0 = C[m,c] = tf32r((relu?)(v + bias))
//        1 = atomicAdd(inc[b, snk[e], c], v + bias)
//        2 = ns[m, 2+c] += v + bias; ns_tf = tf32r(new)   (c < 254)
// ---------------------------------------------------------------------------
template <int AMODE>
__device__ __forceinline__ void load_chunk(
    int c, uint32_t sb, int tid, int m0, int n0, int bIdx,
    const float* __restrict__ A, const float* __restrict__ Wt,
    const float* __restrict__ nsrc, const float* __restrict__ incsrc,
    const int* sSrc, const int* sSnk, int Ncol) {
    const int kt = c * BKv;
    const uint32_t abuf = sb + (uint32_t)(c & 1) * BUFBYTES;
    const uint32_t bbuf = abuf + ABYTES_;
    // A tile: 128 rows x 32 floats (128B rows, SW128 swizzle at 16B granularity)
#pragma unroll
    for (int j = 0; j < 4; j++) {
        int idx = tid + 256 * j;                 // 0..1023
        int row = idx >> 3, c4 = idx & 7;
        uint32_t dst = abuf + (uint32_t)(row * 128 + ((c4 * 16) ^ ((row & 7) << 4)));
        const float* src;
        if (AMODE == 0) {
            src = A + (size_t)(m0 + row) * KDIM + kt + c4 * 4;
        } else if (AMODE == 1) {
            int node = (kt < DD) ? sSrc[row] : sSnk[row];
            int cb = (kt < DD) ? kt : (kt - DD);
            src = nsrc + ((size_t)bIdx * NN + node) * DD + cb + c4 * 4;
        } else {
            size_t rg = (size_t)(m0 + row);
            src = (kt < DD) ? (incsrc + rg * DD + kt + c4 * 4)
                            : (nsrc + rg * DD + (kt - DD) + c4 * 4);
        }
        cp16(dst, src, 16);
    }
    // B tile: 256 n-rows x 32 floats, row-guarded (Ncol=254 case -> zero fill)
#pragma unroll
    for (int j = 0; j < 8; j++) {
        int idx = tid + 256 * j;                 // 0..2047
        int row = idx >> 3, c4 = idx & 7;
        uint32_t dst = bbuf + (uint32_t)(row * 128 + ((c4 * 16) ^ ((row & 7) << 4)));
        int nr = n0 + row;
        int ok = nr < Ncol;
        cp16(dst, Wt + (size_t)(ok ? nr : 0) * KDIM + kt + c4 * 4, ok ? 16u : 0u);
    }
    CP_COMMIT();
}

template <int AMODE, int EPI, int RELU>
__global__ __launch_bounds__(256, 1)
void gemm_mma(const float* __restrict__ A, const float* __restrict__ Wt,
              const float* __restrict__ bias, float* __restrict__ C,
              const int* __restrict__ esrc, const int* __restrict__ esnk,
              const float* __restrict__ nsrc, const float* __restrict__ incsrc,
              float* __restrict__ nsdst, float* __restrict__ nstf,
              int M, int Ncol) {
    extern __shared__ __align__(16) char smem[];
    const uint32_t sb = smem_u32(smem);
    const int tid = threadIdx.x;
    const int wid = tid >> 5, lane = tid & 31;
    const int g = lane >> 2, t4 = lane & 3;
    const int wm = wid >> 2, wn = wid & 3;       // 2 x 4 warp grid
    const int m0 = blockIdx.y * TMv;
    const int n0 = blockIdx.x * TNv;
    const int bIdx = (AMODE == 1 || EPI == 1) ? (m0 / EE) : 0;
    int* sSrc = (int*)(smem + SOFF_SRC);
    int* sSnk = (int*)(smem + SOFF_SNK);

    if (AMODE == 1 || EPI == 1) {
        if (tid < TMv) {
            int e = (m0 - bIdx * EE) + tid;
            if (AMODE == 1) sSrc[tid] = esrc[e];
            sSnk[tid] = esnk[e];
        }
        __syncthreads();
    }

    // ldmatrix lane-constant address components
    const int sub = lane >> 3, r = lane & 7;
    // A: row = wm*64 + mt*16 + (sub&1)*8 + r ; kbyte = (kk*32 + (sub>>1)*16) ^ (r<<4)
    const uint32_t aRowOff = (uint32_t)((wm * 64 + (sub & 1) * 8 + r) * 128);
    uint32_t aK[4];
    // B: n = wn*64 + p2*16 + (sub>>1)*8 + r ; kbyte = (kk*32 + (sub&1)*16) ^ (r<<4)
    const uint32_t bRowOff = (uint32_t)((wn * 64 + (sub >> 1) * 8 + r) * 128);
    uint32_t bK[4];
#pragma unroll
    for (int kk = 0; kk < 4; kk++) {
        aK[kk] = (uint32_t)((kk * 32 + (sub >> 1) * 16) ^ (r << 4));
        bK[kk] = (uint32_t)((kk * 32 + (sub & 1) * 16) ^ (r << 4));
    }

    float acc[4][8][4];
#pragma unroll
    for (int mt = 0; mt < 4; mt++)
#pragma unroll
        for (int nt = 0; nt < 8; nt++)
#pragma unroll
            for (int i = 0; i < 4; i++) acc[mt][nt][i] = 0.f;

    load_chunk<AMODE>(0, sb, tid, m0, n0, bIdx, A, Wt, nsrc, incsrc, sSrc, sSnk, Ncol);
    load_chunk<AMODE>(1, sb, tid, m0, n0, bIdx, A, Wt, nsrc, incsrc, sSrc, sSnk, Ncol);

#pragma unroll 1
    for (int c = 0; c < NCHUNK; c++) {
        if (c < NCHUNK - 1) asm volatile("cp.async.wait_group 1;" ::: "memory");
        else                asm volatile("cp.async.wait_group 0;" ::: "memory");
        __syncthreads();

        const uint32_t abuf = sb + (uint32_t)(c & 1) * BUFBYTES;
        const uint32_t bbuf = abuf + ABYTES_;
#pragma unroll
        for (int kk = 0; kk < 4; kk++) {
            uint32_t a[4][4];
#pragma unroll
            for (int mt = 0; mt < 4; mt++)
                LDSM4(a[mt][0], a[mt][1], a[mt][2], a[mt][3],
                      abuf + aRowOff + (uint32_t)(mt * 2048) + aK[kk]);
            uint32_t b[8][2];
#pragma unroll
            for (int p2 = 0; p2 < 4; p2++)
                LDSM4(b[2 * p2][0], b[2 * p2][1], b[2 * p2 + 1][0], b[2 * p2 + 1][1],
                      bbuf + bRowOff + (uint32_t)(p2 * 2048) + bK[kk]);
#pragma unroll
            for (int mt = 0; mt < 4; mt++)
#pragma unroll
                for (int nt = 0; nt < 8; nt++) mma1688(acc[mt][nt], a[mt], b[nt]);
        }
        __syncthreads();
        if (c + 2 < NCHUNK)
            load_chunk<AMODE>(c + 2, sb, tid, m0, n0, bIdx, A, Wt, nsrc, incsrc, sSrc, sSnk, Ncol);
    }

    // Epilogue: thread owns rows {rl0, rl0+8} x cols {cc, cc+1} per (mt, nt)
#pragma unroll
    for (int mt = 0; mt < 4; mt++) {
        const int rl0 = wm * 64 + mt * 16 + g;
#pragma unroll
        for (int nt = 0; nt < 8; nt++) {
            const int cc = n0 + wn * 64 + nt * 8 + t4 * 2;
            float v0 = acc[mt][nt][0] + bias[cc];
            float v1 = acc[mt][nt][1] + bias[cc + 1];
            float v2 = acc[mt][nt][2] + bias[cc];
            float v3 = acc[mt][nt][3] + bias[cc + 1];
            if (RELU) {
                v0 = fmaxf(v0, 0.f); v1 = fmaxf(v1, 0.f);
                v2 = fmaxf(v2, 0.f); v3 = fmaxf(v3, 0.f);
            }
            if (EPI == 0) {
                float2 s0 = make_float2(tf32r(v0), tf32r(v1));
                float2 s1 = make_float2(tf32r(v2), tf32r(v3));
                *(float2*)(C + (size_t)(m0 + rl0) * Ncol + cc) = s0;
                *(float2*)(C + (size_t)(m0 + rl0 + 8) * Ncol + cc) = s1;
            } else if (EPI == 1) {
                float* d0 = C + ((size_t)bIdx * NN + sSnk[rl0]) * MSGD + cc;
                float* d1 = C + ((size_t)bIdx * NN + sSnk[rl0 + 8]) * MSGD + cc;
                atomicAdd(d0, v0); atomicAdd(d0 + 1, v1);
                atomicAdd(d1, v2); atomicAdd(d1 + 1, v3);
            } else {
                size_t r0 = (size_t)(m0 + rl0) * DD + (DD - UPDD);
                size_t r1 = (size_t)(m0 + rl0 + 8) * DD + (DD - UPDD);
                if (cc < UPDD) {
                    float u0 = nsdst[r0 + cc] + v0; nsdst[r0 + cc] = u0; nstf[r0 + cc] = tf32r(u0);
                    float u2 = nsdst[r1 + cc] + v2; nsdst[r1 + cc] = u2; nstf[r1 + cc] = tf32r(u2);
                }
                if (cc + 1 < UPDD) {
                    float u1 = nsdst[r0 + cc + 1] + v1; nsdst[r0 + cc + 1] = u1; nstf[r0 + cc + 1] = tf32r(u1);
                    float u3 = nsdst[r1 + cc + 1] + v3; nsdst[r1 + cc + 1] = u3; nstf[r1 + cc + 1] = tf32r(u3);
                }
            }
        }
    }
}

// ---------------------------------------------------------------------------
// Glue kernels
// ---------------------------------------------------------------------------
__global__ void copy_round_kernel(float4* __restrict__ dst, float4* __restrict__ dtf,
                                  const float4* __restrict__ src, int n4) {
    int i = blockIdx.x * blockDim.x + threadIdx.x;
    if (i >= n4) return;
    float4 v = src[i];
    dst[i] = v;
    dtf[i] = make_float4(tf32r(v.x), tf32r(v.y), tf32r(v.z), tf32r(v.w));
}
__global__ void round4_kernel(float4* __restrict__ dst, const float4* __restrict__ src, int n4) {
    int i = blockIdx.x * blockDim.x + threadIdx.x;
    if (i >= n4) return;
    float4 v = src[i];
    dst[i] = make_float4(tf32r(v.x), tf32r(v.y), tf32r(v.z), tf32r(v.w));
}
__global__ void zero4_kernel(float4* __restrict__ dst, int n4) {
    int i = blockIdx.x * blockDim.x + threadIdx.x;
    if (i < n4) dst[i] = make_float4(0.f, 0.f, 0.f, 0.f);
}
// out[n*K+k] = tf32_round(in[k*N+n])
__global__ void transpose_kernel(const float* __restrict__ in, float* __restrict__ out,
                                 int K, int N) {
    __shared__ float t[32][33];
    int k0 = blockIdx.y * 32, n0 = blockIdx.x * 32;
    int tx = threadIdx.x, ty = threadIdx.y;
    for (int i = ty; i < 32; i += 8) {
        int k = k0 + i, n = n0 + tx;
        t[i][tx] = (k < K && n < N) ? in[(size_t)k * N + n] : 0.f;
    }
    __syncthreads();
    for (int i = ty; i < 32; i += 8) {
        int n = n0 + i, k = k0 + tx;
        if (n < N && k < K) out[(size_t)n * K + k] = tf32r(t[tx][i]);
    }
}

// ---------------------------------------------------------------------------
// Extraction: out[b,p,d] += sum over n-chunk of attn[b,p,n] * ns[b,n,d]
// grid: x = D/128 (d-tile), z = BB*32 (batch, n-chunk of 128). M=64, N=128, K=128.
// ---------------------------------------------------------------------------
__global__ __launch_bounds__(256)
void extract_kernel(const float* __restrict__ attn, const float* __restrict__ ns,
                    float* __restrict__ out) {
    const int b = blockIdx.z >> 5, kc = blockIdx.z & 31;
    const float* Ab = attn + (size_t)b * PP * NN + (size_t)kc * 128;      // [64 x 128], row stride NN
    const float* Bb = ns + (size_t)b * NN * DD + (size_t)kc * 128 * DD
                      + (size_t)blockIdx.x * 128;                          // [128 x 128], row stride DD
    float* Cb = out + (size_t)b * PP * DD + (size_t)blockIdx.x * 128;

    __shared__ __align__(16) float sA[8][72];    // [k][p]
    __shared__ __align__(16) float sB[8][132];   // [k][d]
    const int tid = threadIdx.x;
    const int tx = tid & 15, ty = tid >> 4;      // tx -> d (8 each), ty -> p (4 each)

    float acc[4][8];
#pragma unroll
    for (int i = 0; i < 4; i++)
#pragma unroll
        for (int j = 0; j < 8; j++) acc[i][j] = 0.f;

    for (int kt = 0; kt < 128; kt += 8) {
        // stage A: 64 p x 8 k
        {
            int p = tid >> 2, kp = (tid & 3) * 2;
            float2 v = *(const float2*)(Ab + (size_t)p * NN + kt + kp);
            sA[kp][p] = v.x; sA[kp + 1][p] = v.y;
        }
        // stage B: 8 k x 128 d
        {
            int k = tid >> 5, d4 = (tid & 31) * 4;
            *(float4*)&sB[k][d4] = *(const float4*)(Bb + (size_t)(kt + k) * DD + d4);
        }
        __syncthreads();
#pragma unroll
        for (int kk = 0; kk < 8; kk++) {
            float a[4], bb[8];
#pragma unroll
            for (int i = 0; i < 4; i++) a[i] = sA[kk][ty * 4 + i];
#pragma unroll
            for (int j = 0; j < 8; j++) bb[j] = sB[kk][tx * 8 + j];
#pragma unroll
            for (int i = 0; i < 4; i++)
#pragma unroll
                for (int j = 0; j < 8; j++) acc[i][j] += a[i] * bb[j];
        }
        __syncthreads();
    }
#pragma unroll
    for (int i = 0; i < 4; i++) {
        int p = ty * 4 + i;
#pragma unroll
        for (int j = 0; j < 8; j++)
            atomicAdd(Cb + (size_t)p * DD + tx * 8 + j, acc[i][j]);
    }
}

// ---------------------------------------------------------------------------
// Launcher
// ---------------------------------------------------------------------------
extern "C" void kernel_launch(void* const* d_in, const int* in_sizes, int n_in,
                              void* d_out, int out_size) {
    (void)in_sizes; (void)n_in;
    const float* nodes = (const float*)d_in[0];
    const float* attn  = (const float*)d_in[1];
    const float* We1   = (const float*)d_in[2];
    const float* be1   = (const float*)d_in[3];
    const float* We2   = (const float*)d_in[4];
    const float* be2   = (const float*)d_in[5];
    const float* Wn1   = (const float*)d_in[6];
    const float* bn1   = (const float*)d_in[7];
    const float* Wn2   = (const float*)d_in[8];
    const float* bn2   = (const float*)d_in[9];
    const int*   esrc  = (const int*)d_in[10];
    const int*   esnk  = (const int*)d_in[11];
    float*       out   = (float*)d_out;

    float *ns, *nstf, *he, *inc, *inctf, *hn, *wte1, *wte2, *wtn1, *wtn2;
    cudaGetSymbolAddress((void**)&ns,    g_ns);
    cudaGetSymbolAddress((void**)&nstf,  g_nstf);
    cudaGetSymbolAddress((void**)&he,    g_he);
    cudaGetSymbolAddress((void**)&inc,   g_inc);
    cudaGetSymbolAddress((void**)&inctf, g_inctf);
    cudaGetSymbolAddress((void**)&hn,    g_hn);
    cudaGetSymbolAddress((void**)&wte1,  g_wte1);
    cudaGetSymbolAddress((void**)&wte2,  g_wte2);
    cudaGetSymbolAddress((void**)&wtn1,  g_wtn1);
    cudaGetSymbolAddress((void**)&wtn2,  g_wtn2);

    cudaFuncSetAttribute(gemm_mma<1, 0, 1>, cudaFuncAttributeMaxDynamicSharedMemorySize, SMEM_BYTES);
    cudaFuncSetAttribute(gemm_mma<0, 1, 0>, cudaFuncAttributeMaxDynamicSharedMemorySize, SMEM_BYTES);
    cudaFuncSetAttribute(gemm_mma<2, 0, 1>, cudaFuncAttributeMaxDynamicSharedMemorySize, SMEM_BYTES);
    cudaFuncSetAttribute(gemm_mma<0, 2, 0>, cudaFuncAttributeMaxDynamicSharedMemorySize, SMEM_BYTES);

    const int T = 256;
    // Pre-transpose weights to [N,K] K-major, rounded to tf32
    transpose_kernel<<<dim3(HH / 32, KDIM / 32), dim3(32, 8)>>>(We1, wte1, KDIM, HH);
    transpose_kernel<<<dim3(MSGD / 32, KDIM / 32), dim3(32, 8)>>>(We2, wte2, HH, MSGD);
    transpose_kernel<<<dim3(HH / 32, KDIM / 32), dim3(32, 8)>>>(Wn1, wtn1, KDIM, HH);
    transpose_kernel<<<dim3((UPDD + 31) / 32, KDIM / 32), dim3(32, 8)>>>(Wn2, wtn2, HH, UPDD);
    // ns (fp32) + ns_tf (rounded)
    {
        int n4 = BB * NN * DD / 4;
        copy_round_kernel<<<(n4 + T - 1) / T, T>>>((float4*)ns, (float4*)nstf,
                                                   (const float4*)nodes, n4);
    }

    const int ME = BB * EE;  // 131072
    const int MN = BB * NN;  // 32768

    for (int step = 0; step < STEPS; step++) {
        {
            int n4 = BB * NN * MSGD / 4;
            zero4_kernel<<<(n4 + T - 1) / T, T>>>((float4*)inc, n4);
        }
        // GEMM1: he = tf32r(relu(gather(ns_tf) @ W_e1 + b_e1))   [131072 x 512 x 512]
        gemm_mma<1, 0, 1><<<dim3(HH / TNv, ME / TMv), 256, SMEM_BYTES>>>(
            nullptr, wte1, be1, he, esrc, esnk, nstf, nullptr, nullptr, nullptr, ME, HH);
        // GEMM2: inc[snk] += he @ W_e2 + b_e2                    [131072 x 512 x 256]
        gemm_mma<0, 1, 0><<<dim3(MSGD / TNv, ME / TMv), 256, SMEM_BYTES>>>(
            he, wte2, be2, inc, esrc, esnk, nullptr, nullptr, nullptr, nullptr, ME, MSGD);
        // round incoming to tf32 shadow
        {
            int n4 = BB * NN * MSGD / 4;
            round4_kernel<<<(n4 + T - 1) / T, T>>>((float4*)inctf, (const float4*)inc, n4);
        }
        // GEMM3: hn = tf32r(relu(concat(inc_tf, ns_tf) @ W_n1 + b_n1))  [32768 x 512 x 512]
        gemm_mma<2, 0, 1><<<dim3(HH / TNv, MN / TMv), 256, SMEM_BYTES>>>(
            nullptr, wtn1, bn1, hn, nullptr, nullptr, nstf, inctf, nullptr, nullptr, MN, HH);
        // GEMM4: ns[:, 2:] += hn @ W_n2 + b_n2 ; ns_tf refresh    [32768 x 512 x 254]
        gemm_mma<0, 2, 0><<<dim3(1, MN / TMv), 256, SMEM_BYTES>>>(
            hn, wtn2, bn2, nullptr, nullptr, nullptr, nullptr, nullptr, ns, nstf, MN, UPDD);
    }

    // extraction: out[b,p,d] = sum_n attn[b,p,n] * ns[b,n,d]  (fp32, split-K + atomics)
    {
        int n4 = BB * PP * DD / 4;
        zero4_kernel<<<(n4 + T - 1) / T, T>>>((float4*)out, n4);
        extract_kernel<<<dim3(DD / 128, 1, BB * 32), 256>>>(attn, ns, out);
    }
}

// round 8
// speedup vs baseline: 6.3350x; 1.0078x over previous
#include <cuda_runtime.h>
#include <cstdint>

// Problem constants
#define BB   8
#define NN   4096
#define EE   16384
#define PP   64
#define DD   256
#define HH   512
#define MSGD 256
#define UPDD 254
#define STEPS 3
#define KDIM 512

// Tiling: CTA 128x256, 8 warps (2 row x 4 col), warp tile 64x64, BK=32
#define TMv 128
#define TNv 256
#define BKv 32
#define NCHUNK (KDIM / BKv)          // 16
#define STAGES 4
#define ABYTES_ (TMv * 128)          // 16384 (128B per row of 32 floats)
#define BBYTES_ (TNv * 128)          // 32768
#define BUFBYTES (ABYTES_ + BBYTES_) // 49152
#define SOFF_SRC (STAGES * BUFBYTES)       // 196608
#define SOFF_SNK (SOFF_SRC + 512)
#define SMEM_BYTES (SOFF_SNK + 512)        // 197632

// ---------------------------------------------------------------------------
// Scratch (static device globals — no runtime allocation)
// ---------------------------------------------------------------------------
__device__ float g_ns   [BB * NN * DD];
__device__ float g_nstf [BB * NN * DD];
__device__ float g_he   [(size_t)BB * EE * HH];
__device__ float g_inc  [BB * NN * MSGD];
__device__ float g_inctf[BB * NN * MSGD];
__device__ float g_hn   [BB * NN * HH];
__device__ float g_wte1[HH   * KDIM];
__device__ float g_wte2[MSGD * KDIM];
__device__ float g_wtn1[HH   * KDIM];
__device__ float g_wtn2[UPDD * KDIM];

// ---------------------------------------------------------------------------
// Helpers (portable PTX only: cp.async + ldmatrix + mma.sync tf32)
// ---------------------------------------------------------------------------
__device__ __forceinline__ uint32_t smem_u32(const void* p) {
    uint32_t a;
    asm("{ .reg .u64 t; cvta.to.shared.u64 t, %1; cvt.u32.u64 %0, t; }" : "=r"(a) : "l"(p));
    return a;
}
__device__ __forceinline__ void cp16(uint32_t dst, const void* src, uint32_t sz) {
    asm volatile("cp.async.ca.shared.global [%0], [%1], 16, %2;\n" :: "r"(dst), "l"(src), "r"(sz));
}
#define CP_COMMIT() asm volatile("cp.async.commit_group;\n" ::: "memory")
template <int N>
__device__ __forceinline__ void cp_wait() {
    asm volatile("cp.async.wait_group %0;" :: "n"(N) : "memory");
}

__device__ __forceinline__ uint32_t f2tf32(float f) {
    uint32_t u;
    asm("cvt.rna.tf32.f32 %0, %1;" : "=r"(u) : "f"(f));
    return u;
}
__device__ __forceinline__ float tf32r(float f) { return __uint_as_float(f2tf32(f)); }

__device__ __forceinline__ void mma1688(float* c, const uint32_t* a, const uint32_t* b) {
    asm volatile(
        "mma.sync.aligned.m16n8k8.row.col.f32.tf32.tf32.f32 "
        "{%0,%1,%2,%3}, {%4,%5,%6,%7}, {%8,%9}, {%0,%1,%2,%3};"
        : "+f"(c[0]), "+f"(c[1]), "+f"(c[2]), "+f"(c[3])
        : "r"(a[0]), "r"(a[1]), "r"(a[2]), "r"(a[3]), "r"(b[0]), "r"(b[1]));
}
#define LDSM4(r0, r1, r2, r3, a) \
    asm volatile("ldmatrix.sync.aligned.m8n8.x4.shared.b16 {%0,%1,%2,%3}, [%4];" \
        : "=r"(r0), "=r"(r1), "=r"(r2), "=r"(r3) : "r"(a))

// ---------------------------------------------------------------------------
// tf32 mma.sync GEMM with fused A-sources and fused epilogues.
// AMODE: 0 = direct A[m,k] (pre-rounded tf32)
//        1 = edge gather from ns_tf: k<256 -> src[e], k>=256 -> snk[e]
//        2 = node concat: k<256 -> inc_tf[m], k>=256 -> ns_tf[m]
// EPI:   0 = C[m,c] = tf32r((relu?)(v + bias))
//        1 = atomicAdd(inc[b, snk[e], c], v + bias)
//        2 = ns[m, 2+c] += v + bias; ns_tf = tf32r(new)   (c < 254)
// ---------------------------------------------------------------------------
template <int AMODE>
__device__ __forceinline__ void load_chunk(
    int c, uint32_t sb, int tid, int m0, int n0, int bIdx,
    const float* __restrict__ A, const float* __restrict__ Wt,
    const float* __restrict__ nsrc, const float* __restrict__ incsrc,
    const int* sSrc, const int* sSnk, int Ncol) {
    const int kt = c * BKv;
    const uint32_t abuf = sb + (uint32_t)(c & (STAGES - 1)) * BUFBYTES;
    const uint32_t bbuf = abuf + ABYTES_;
    // A tile: 128 rows x 32 floats (128B rows, XOR swizzle at 16B granularity)
#pragma unroll
    for (int j = 0; j < 4; j++) {
        int idx = tid + 256 * j;                 // 0..1023
        int row = idx >> 3, c4 = idx & 7;
        uint32_t dst = abuf + (uint32_t)(row * 128 + ((c4 * 16) ^ ((row & 7) << 4)));
        const float* src;
        if (AMODE == 0) {
            src = A + (size_t)(m0 + row) * KDIM + kt + c4 * 4;
        } else if (AMODE == 1) {
            int node = (kt < DD) ? sSrc[row] : sSnk[row];
            int cb = (kt < DD) ? kt : (kt - DD);
            src = nsrc + ((size_t)bIdx * NN + node) * DD + cb + c4 * 4;
        } else {
            size_t rg = (size_t)(m0 + row);
            src = (kt < DD) ? (incsrc + rg * DD + kt + c4 * 4)
                            : (nsrc + rg * DD + (kt - DD) + c4 * 4);
        }
        cp16(dst, src, 16);
    }
    // B tile: 256 n-rows x 32 floats, row-guarded (Ncol=254 case -> zero fill)
#pragma unroll
    for (int j = 0; j < 8; j++) {
        int idx = tid + 256 * j;                 // 0..2047
        int row = idx >> 3, c4 = idx & 7;
        uint32_t dst = bbuf + (uint32_t)(row * 128 + ((c4 * 16) ^ ((row & 7) << 4)));
        int nr = n0 + row;
        int ok = nr < Ncol;
        cp16(dst, Wt + (size_t)(ok ? nr : 0) * KDIM + kt + c4 * 4, ok ? 16u : 0u);
    }
    CP_COMMIT();
}

template <int AMODE, int EPI, int RELU>
__global__ __launch_bounds__(256, 1)
void gemm_mma(const float* __restrict__ A, const float* __restrict__ Wt,
              const float* __restrict__ bias, float* __restrict__ C,
              const int* __restrict__ esrc, const int* __restrict__ esnk,
              const float* __restrict__ nsrc, const float* __restrict__ incsrc,
              float* __restrict__ nsdst, float* __restrict__ nstf,
              int M, int Ncol) {
    extern __shared__ __align__(16) char smem[];
    const uint32_t sb = smem_u32(smem);
    const int tid = threadIdx.x;
    const int wid = tid >> 5, lane = tid & 31;
    const int g = lane >> 2, t4 = lane & 3;
    const int wm = wid >> 2, wn = wid & 3;       // 2 x 4 warp grid
    const int m0 = blockIdx.y * TMv;
    const int n0 = blockIdx.x * TNv;
    const int bIdx = (AMODE == 1 || EPI == 1) ? (m0 / EE) : 0;
    int* sSrc = (int*)(smem + SOFF_SRC);
    int* sSnk = (int*)(smem + SOFF_SNK);

    if (AMODE == 1 || EPI == 1) {
        if (tid < TMv) {
            int e = (m0 - bIdx * EE) + tid;
            if (AMODE == 1) sSrc[tid] = esrc[e];
            sSnk[tid] = esnk[e];
        }
        __syncthreads();
    }

    // ldmatrix lane-constant address components
    const int sub = lane >> 3, r = lane & 7;
    const uint32_t aRowOff = (uint32_t)((wm * 64 + (sub & 1) * 8 + r) * 128);
    const uint32_t bRowOff = (uint32_t)((wn * 64 + (sub >> 1) * 8 + r) * 128);
    uint32_t aK[4], bK[4];
#pragma unroll
    for (int kk = 0; kk < 4; kk++) {
        aK[kk] = (uint32_t)((kk * 32 + (sub >> 1) * 16) ^ (r << 4));
        bK[kk] = (uint32_t)((kk * 32 + (sub & 1) * 16) ^ (r << 4));
    }

    float acc[4][8][4];
#pragma unroll
    for (int mt = 0; mt < 4; mt++)
#pragma unroll
        for (int nt = 0; nt < 8; nt++)
#pragma unroll
            for (int i = 0; i < 4; i++) acc[mt][nt][i] = 0.f;

    // Prologue: fill STAGES-1 buffers
#pragma unroll
    for (int c = 0; c < STAGES - 1; c++)
        load_chunk<AMODE>(c, sb, tid, m0, n0, bIdx, A, Wt, nsrc, incsrc, sSrc, sSnk, Ncol);

#pragma unroll 1
    for (int c = 0; c < NCHUNK; c++) {
        cp_wait<STAGES - 2>();
        __syncthreads();   // chunk c ready for all; chunk c-1 consumed by all

        // Issue the next load BEFORE compute so DMA overlaps MMA.
        if (c + STAGES - 1 < NCHUNK)
            load_chunk<AMODE>(c + STAGES - 1, sb, tid, m0, n0, bIdx,
                              A, Wt, nsrc, incsrc, sSrc, sSnk, Ncol);

        const uint32_t abuf = sb + (uint32_t)(c & (STAGES - 1)) * BUFBYTES;
        const uint32_t bbuf = abuf + ABYTES_;
#pragma unroll
        for (int kk = 0; kk < 4; kk++) {
            uint32_t a[4][4];
#pragma unroll
            for (int mt = 0; mt < 4; mt++)
                LDSM4(a[mt][0], a[mt][1], a[mt][2], a[mt][3],
                      abuf + aRowOff + (uint32_t)(mt * 2048) + aK[kk]);
            uint32_t b[8][2];
#pragma unroll
            for (int p2 = 0; p2 < 4; p2++)
                LDSM4(b[2 * p2][0], b[2 * p2][1], b[2 * p2 + 1][0], b[2 * p2 + 1][1],
                      bbuf + bRowOff + (uint32_t)(p2 * 2048) + bK[kk]);
#pragma unroll
            for (int mt = 0; mt < 4; mt++)
#pragma unroll
                for (int nt = 0; nt < 8; nt++) mma1688(acc[mt][nt], a[mt], b[nt]);
        }
    }

    // Epilogue: thread owns rows {rl0, rl0+8} x cols {cc, cc+1} per (mt, nt)
#pragma unroll
    for (int mt = 0; mt < 4; mt++) {
        const int rl0 = wm * 64 + mt * 16 + g;
#pragma unroll
        for (int nt = 0; nt < 8; nt++) {
            const int cc = n0 + wn * 64 + nt * 8 + t4 * 2;
            const float b0v = bias[cc], b1v = bias[cc + 1];
            float v0 = acc[mt][nt][0] + b0v;
            float v1 = acc[mt][nt][1] + b1v;
            float v2 = acc[mt][nt][2] + b0v;
            float v3 = acc[mt][nt][3] + b1v;
            if (RELU) {
                v0 = fmaxf(v0, 0.f); v1 = fmaxf(v1, 0.f);
                v2 = fmaxf(v2, 0.f); v3 = fmaxf(v3, 0.f);
            }
            if (EPI == 0) {
                float2 s0 = make_float2(tf32r(v0), tf32r(v1));
                float2 s1 = make_float2(tf32r(v2), tf32r(v3));
                *(float2*)(C + (size_t)(m0 + rl0) * Ncol + cc) = s0;
                *(float2*)(C + (size_t)(m0 + rl0 + 8) * Ncol + cc) = s1;
            } else if (EPI == 1) {
                float* d0 = C + ((size_t)bIdx * NN + sSnk[rl0]) * MSGD + cc;
                float* d1 = C + ((size_t)bIdx * NN + sSnk[rl0 + 8]) * MSGD + cc;
                atomicAdd(d0, v0); atomicAdd(d0 + 1, v1);
                atomicAdd(d1, v2); atomicAdd(d1 + 1, v3);
            } else {
                size_t r0 = (size_t)(m0 + rl0) * DD + (DD - UPDD);
                size_t r1 = (size_t)(m0 + rl0 + 8) * DD + (DD - UPDD);
                if (cc < UPDD) {
                    float u0 = nsdst[r0 + cc] + v0; nsdst[r0 + cc] = u0; nstf[r0 + cc] = tf32r(u0);
                    float u2 = nsdst[r1 + cc] + v2; nsdst[r1 + cc] = u2; nstf[r1 + cc] = tf32r(u2);
                }
                if (cc + 1 < UPDD) {
                    float u1 = nsdst[r0 + cc + 1] + v1; nsdst[r0 + cc + 1] = u1; nstf[r0 + cc + 1] = tf32r(u1);
                    float u3 = nsdst[r1 + cc + 1] + v3; nsdst[r1 + cc + 1] = u3; nstf[r1 + cc + 1] = tf32r(u3);
                }
            }
        }
    }
}

// ---------------------------------------------------------------------------
// Glue kernels
// ---------------------------------------------------------------------------
__global__ void copy_round_kernel(float4* __restrict__ dst, float4* __restrict__ dtf,
                                  const float4* __restrict__ src, int n4) {
    int i = blockIdx.x * blockDim.x + threadIdx.x;
    if (i >= n4) return;
    float4 v = src[i];
    dst[i] = v;
    dtf[i] = make_float4(tf32r(v.x), tf32r(v.y), tf32r(v.z), tf32r(v.w));
}
__global__ void round4_kernel(float4* __restrict__ dst, const float4* __restrict__ src, int n4) {
    int i = blockIdx.x * blockDim.x + threadIdx.x;
    if (i >= n4) return;
    float4 v = src[i];
    dst[i] = make_float4(tf32r(v.x), tf32r(v.y), tf32r(v.z), tf32r(v.w));
}
__global__ void zero4_kernel(float4* __restrict__ dst, int n4) {
    int i = blockIdx.x * blockDim.x + threadIdx.x;
    if (i < n4) dst[i] = make_float4(0.f, 0.f, 0.f, 0.f);
}
// out[n*K+k] = tf32_round(in[k*N+n])
__global__ void transpose_kernel(const float* __restrict__ in, float* __restrict__ out,
                                 int K, int N) {
    __shared__ float t[32][33];
    int k0 = blockIdx.y * 32, n0 = blockIdx.x * 32;
    int tx = threadIdx.x, ty = threadIdx.y;
    for (int i = ty; i < 32; i += 8) {
        int k = k0 + i, n = n0 + tx;
        t[i][tx] = (k < K && n < N) ? in[(size_t)k * N + n] : 0.f;
    }
    __syncthreads();
    for (int i = ty; i < 32; i += 8) {
        int n = n0 + i, k = k0 + tx;
        if (n < N && k < K) out[(size_t)n * K + k] = tf32r(t[tx][i]);
    }
}

// ---------------------------------------------------------------------------
// Extraction: out[b,p,d] += sum over n-chunk of attn[b,p,n] * ns[b,n,d]
// grid: x = D/128 (d-tile), z = BB*32 (batch, n-chunk of 128). M=64, N=128, K=128.
// ---------------------------------------------------------------------------
__global__ __launch_bounds__(256)
void extract_kernel(const float* __restrict__ attn, const float* __restrict__ ns,
                    float* __restrict__ out) {
    const int b = blockIdx.z >> 5, kc = blockIdx.z & 31;
    const float* Ab = attn + (size_t)b * PP * NN + (size_t)kc * 128;
    const float* Bb = ns + (size_t)b * NN * DD + (size_t)kc * 128 * DD
                      + (size_t)blockIdx.x * 128;
    float* Cb = out + (size_t)b * PP * DD + (size_t)blockIdx.x * 128;

    __shared__ __align__(16) float sA[8][72];
    __shared__ __align__(16) float sB[8][132];
    const int tid = threadIdx.x;
    const int tx = tid & 15, ty = tid >> 4;

    float acc[4][8];
#pragma unroll
    for (int i = 0; i < 4; i++)
#pragma unroll
        for (int j = 0; j < 8; j++) acc[i][j] = 0.f;

    for (int kt = 0; kt < 128; kt += 8) {
        {
            int p = tid >> 2, kp = (tid & 3) * 2;
            float2 v = *(const float2*)(Ab + (size_t)p * NN + kt + kp);
            sA[kp][p] = v.x; sA[kp + 1][p] = v.y;
        }
        {
            int k = tid >> 5, d4 = (tid & 31) * 4;
            *(float4*)&sB[k][d4] = *(const float4*)(Bb + (size_t)(kt + k) * DD + d4);
        }
        __syncthreads();
#pragma unroll
        for (int kk = 0; kk < 8; kk++) {
            float a[4], bb[8];
#pragma unroll
            for (int i = 0; i < 4; i++) a[i] = sA[kk][ty * 4 + i];
#pragma unroll
            for (int j = 0; j < 8; j++) bb[j] = sB[kk][tx * 8 + j];
#pragma unroll
            for (int i = 0; i < 4; i++)
#pragma unroll
                for (int j = 0; j < 8; j++) acc[i][j] += a[i] * bb[j];
        }
        __syncthreads();
    }
#pragma unroll
    for (int i = 0; i < 4; i++) {
        int p = ty * 4 + i;
#pragma unroll
        for (int j = 0; j < 8; j++)
            atomicAdd(Cb + (size_t)p * DD + tx * 8 + j, acc[i][j]);
    }
}

// ---------------------------------------------------------------------------
// Launcher
// ---------------------------------------------------------------------------
extern "C" void kernel_launch(void* const* d_in, const int* in_sizes, int n_in,
                              void* d_out, int out_size) {
    (void)in_sizes; (void)n_in;
    const float* nodes = (const float*)d_in[0];
    const float* attn  = (const float*)d_in[1];
    const float* We1   = (const float*)d_in[2];
    const float* be1   = (const float*)d_in[3];
    const float* We2   = (const float*)d_in[4];
    const float* be2   = (const float*)d_in[5];
    const float* Wn1   = (const float*)d_in[6];
    const float* bn1   = (const float*)d_in[7];
    const float* Wn2   = (const float*)d_in[8];
    const float* bn2   = (const float*)d_in[9];
    const int*   esrc  = (const int*)d_in[10];
    const int*   esnk  = (const int*)d_in[11];
    float*       out   = (float*)d_out;

    float *ns, *nstf, *he, *inc, *inctf, *hn, *wte1, *wte2, *wtn1, *wtn2;
    cudaGetSymbolAddress((void**)&ns,    g_ns);
    cudaGetSymbolAddress((void**)&nstf,  g_nstf);
    cudaGetSymbolAddress((void**)&he,    g_he);
    cudaGetSymbolAddress((void**)&inc,   g_inc);
    cudaGetSymbolAddress((void**)&inctf, g_inctf);
    cudaGetSymbolAddress((void**)&hn,    g_hn);
    cudaGetSymbolAddress((void**)&wte1,  g_wte1);
    cudaGetSymbolAddress((void**)&wte2,  g_wte2);
    cudaGetSymbolAddress((void**)&wtn1,  g_wtn1);
    cudaGetSymbolAddress((void**)&wtn2,  g_wtn2);

    cudaFuncSetAttribute(gemm_mma<1, 0, 1>, cudaFuncAttributeMaxDynamicSharedMemorySize, SMEM_BYTES);
    cudaFuncSetAttribute(gemm_mma<0, 1, 0>, cudaFuncAttributeMaxDynamicSharedMemorySize, SMEM_BYTES);
    cudaFuncSetAttribute(gemm_mma<2, 0, 1>, cudaFuncAttributeMaxDynamicSharedMemorySize, SMEM_BYTES);
    cudaFuncSetAttribute(gemm_mma<0, 2, 0>, cudaFuncAttributeMaxDynamicSharedMemorySize, SMEM_BYTES);

    const int T = 256;
    // Pre-transpose weights to [N,K] K-major, rounded to tf32
    transpose_kernel<<<dim3(HH / 32, KDIM / 32), dim3(32, 8)>>>(We1, wte1, KDIM, HH);
    transpose_kernel<<<dim3(MSGD / 32, KDIM / 32), dim3(32, 8)>>>(We2, wte2, HH, MSGD);
    transpose_kernel<<<dim3(HH / 32, KDIM / 32), dim3(32, 8)>>>(Wn1, wtn1, KDIM, HH);
    transpose_kernel<<<dim3((UPDD + 31) / 32, KDIM / 32), dim3(32, 8)>>>(Wn2, wtn2, HH, UPDD);
    // ns (fp32) + ns_tf (rounded)
    {
        int n4 = BB * NN * DD / 4;
        copy_round_kernel<<<(n4 + T - 1) / T, T>>>((float4*)ns, (float4*)nstf,
                                                   (const float4*)nodes, n4);
    }

    const int ME = BB * EE;  // 131072
    const int MN = BB * NN;  // 32768

    for (int step = 0; step < STEPS; step++) {
        {
            int n4 = BB * NN * MSGD / 4;
            zero4_kernel<<<(n4 + T - 1) / T, T>>>((float4*)inc, n4);
        }
        // GEMM1: he = tf32r(relu(gather(ns_tf) @ W_e1 + b_e1))   [131072 x 512 x 512]
        gemm_mma<1, 0, 1><<<dim3(HH / TNv, ME / TMv), 256, SMEM_BYTES>>>(
            nullptr, wte1, be1, he, esrc, esnk, nstf, nullptr, nullptr, nullptr, ME, HH);
        // GEMM2: inc[snk] += he @ W_e2 + b_e2                    [131072 x 512 x 256]
        gemm_mma<0, 1, 0><<<dim3(MSGD / TNv, ME / TMv), 256, SMEM_BYTES>>>(
            he, wte2, be2, inc, esrc, esnk, nullptr, nullptr, nullptr, nullptr, ME, MSGD);
        // round incoming to tf32 shadow
        {
            int n4 = BB * NN * MSGD / 4;
            round4_kernel<<<(n4 + T - 1) / T, T>>>((float4*)inctf, (const float4*)inc, n4);
        }
        // GEMM3: hn = tf32r(relu(concat(inc_tf, ns_tf) @ W_n1 + b_n1))  [32768 x 512 x 512]
        gemm_mma<2, 0, 1><<<dim3(HH / TNv, MN / TMv), 256, SMEM_BYTES>>>(
            nullptr, wtn1, bn1, hn, nullptr, nullptr, nstf, inctf, nullptr, nullptr, MN, HH);
        // GEMM4: ns[:, 2:] += hn @ W_n2 + b_n2 ; ns_tf refresh    [32768 x 512 x 254]
        gemm_mma<0, 2, 0><<<dim3(1, MN / TMv), 256, SMEM_BYTES>>>(
            hn, wtn2, bn2, nullptr, nullptr, nullptr, nullptr, nullptr, ns, nstf, MN, UPDD);
    }

    // extraction: out[b,p,d] = sum_n attn[b,p,n] * ns[b,n,d]  (fp32, split-K + atomics)
    {
        int n4 = BB * PP * DD / 4;
        zero4_kernel<<<(n4 + T - 1) / T, T>>>((float4*)out, n4);
        extract_kernel<<<dim3(DD / 128, 1, BB * 32), 256>>>(attn, ns, out);
    }
}

// round 9
// speedup vs baseline: 10.1299x; 1.5990x over previous
#include <cuda_runtime.h>
#include <cuda_fp16.h>
#include <cstdint>

// Problem constants
#define BB   8
#define NN   4096
#define EE   16384
#define PP   64
#define DD   256
#define HH   512
#define MSGD 256
#define UPDD 254
#define STEPS 3
#define KDIM 512

// Tiling: CTA 128x256, 8 warps (2 row x 4 col), warp tile 64x64, BK=64 halves
#define TMv 128
#define TNv 256
#define BKh 64                        // k-halves per chunk (128 bytes)
#define NCHUNK (KDIM / BKh)           // 8
#define STAGES 4
#define ABYTES_ (TMv * 128)           // 16384
#define BBYTES_ (TNv * 128)           // 32768
#define BUFBYTES (ABYTES_ + BBYTES_)  // 49152
#define SOFF_SRC (STAGES * BUFBYTES)        // 196608
#define SOFF_SNK (SOFF_SRC + 512)
#define SMEM_BYTES (SOFF_SNK + 512)         // 197632

// ---------------------------------------------------------------------------
// Scratch (static device globals — no runtime allocation)
// ---------------------------------------------------------------------------
__device__ float  g_ns   [BB * NN * DD];           // fp32 node states
__device__ __half g_nstf [BB * NN * DD];           // fp16 shadow of ns
__device__ __half g_he   [(size_t)BB * EE * HH];   // fp16 edge hidden
__device__ float  g_inc  [BB * NN * MSGD];         // fp32 incoming (atomics)
__device__ __half g_inctf[BB * NN * MSGD];         // fp16 shadow
__device__ __half g_hn   [BB * NN * HH];           // fp16 node hidden
__device__ __half g_wte1[HH   * KDIM];
__device__ __half g_wte2[MSGD * KDIM];
__device__ __half g_wtn1[HH   * KDIM];
__device__ __half g_wtn2[UPDD * KDIM];

// ---------------------------------------------------------------------------
// Helpers (portable PTX only: cp.async + ldmatrix + mma.sync fp16)
// ---------------------------------------------------------------------------
__device__ __forceinline__ uint32_t smem_u32(const void* p) {
    uint32_t a;
    asm("{ .reg .u64 t; cvta.to.shared.u64 t, %1; cvt.u32.u64 %0, t; }" : "=r"(a) : "l"(p));
    return a;
}
__device__ __forceinline__ void cp16(uint32_t dst, const void* src, uint32_t sz) {
    asm volatile("cp.async.ca.shared.global [%0], [%1], 16, %2;\n" :: "r"(dst), "l"(src), "r"(sz));
}
#define CP_COMMIT() asm volatile("cp.async.commit_group;\n" ::: "memory")
template <int N>
__device__ __forceinline__ void cp_wait() {
    asm volatile("cp.async.wait_group %0;" :: "n"(N) : "memory");
}

__device__ __forceinline__ void mma16816(float* c, const uint32_t* a, const uint32_t* b) {
    asm volatile(
        "mma.sync.aligned.m16n8k16.row.col.f32.f16.f16.f32 "
        "{%0,%1,%2,%3}, {%4,%5,%6,%7}, {%8,%9}, {%0,%1,%2,%3};"
        : "+f"(c[0]), "+f"(c[1]), "+f"(c[2]), "+f"(c[3])
        : "r"(a[0]), "r"(a[1]), "r"(a[2]), "r"(a[3]), "r"(b[0]), "r"(b[1]));
}
#define LDSM4(r0, r1, r2, r3, a) \
    asm volatile("ldmatrix.sync.aligned.m8n8.x4.shared.b16 {%0,%1,%2,%3}, [%4];" \
        : "=r"(r0), "=r"(r1), "=r"(r2), "=r"(r3) : "r"(a))

// ---------------------------------------------------------------------------
// fp16 mma.sync GEMM (fp32 accum) with fused A-sources and fused epilogues.
// AMODE: 0 = direct A[m,k] (fp16)
//        1 = edge gather from ns_tf: k<256 -> src[e], k>=256 -> snk[e]
//        2 = node concat: k<256 -> inc_tf[m], k>=256 -> ns_tf[m]
// EPI:   0 = Ch[m,c] = fp16((relu?)(v + bias))
//        1 = atomicAdd(incf[b, snk[e], c], v + bias)       (fp32)
//        2 = ns[m, 2+c] += v + bias; ns_tf = fp16(new)     (c < 254)
// ---------------------------------------------------------------------------
template <int AMODE>
__device__ __forceinline__ void load_chunk(
    int c, uint32_t sb, int tid, int m0, int n0, int bIdx,
    const __half* __restrict__ A, const __half* __restrict__ Wt,
    const __half* __restrict__ nsrc, const __half* __restrict__ incsrc,
    const int* sSrc, const int* sSnk, int Ncol) {
    const int kt = c * BKh;                       // in halves
    const uint32_t abuf = sb + (uint32_t)(c & (STAGES - 1)) * BUFBYTES;
    const uint32_t bbuf = abuf + ABYTES_;
    // A tile: 128 rows x 64 halves (128B rows, XOR swizzle at 16B granularity)
#pragma unroll
    for (int j = 0; j < 4; j++) {
        int idx = tid + 256 * j;                  // 0..1023
        int row = idx >> 3, c4 = idx & 7;         // c4: 8 groups of 8 halves
        uint32_t dst = abuf + (uint32_t)(row * 128 + ((c4 * 16) ^ ((row & 7) << 4)));
        const __half* src;
        if (AMODE == 0) {
            src = A + (size_t)(m0 + row) * KDIM + kt + c4 * 8;
        } else if (AMODE == 1) {
            int node = (kt < DD) ? sSrc[row] : sSnk[row];
            int cb = (kt < DD) ? kt : (kt - DD);
            src = nsrc + ((size_t)bIdx * NN + node) * DD + cb + c4 * 8;
        } else {
            size_t rg = (size_t)(m0 + row);
            src = (kt < DD) ? (incsrc + rg * DD + kt + c4 * 8)
                            : (nsrc + rg * DD + (kt - DD) + c4 * 8);
        }
        cp16(dst, src, 16);
    }
    // B tile: 256 n-rows x 64 halves, row-guarded (Ncol=254 case -> zero fill)
#pragma unroll
    for (int j = 0; j < 8; j++) {
        int idx = tid + 256 * j;                  // 0..2047
        int row = idx >> 3, c4 = idx & 7;
        uint32_t dst = bbuf + (uint32_t)(row * 128 + ((c4 * 16) ^ ((row & 7) << 4)));
        int nr = n0 + row;
        int ok = nr < Ncol;
        cp16(dst, Wt + (size_t)(ok ? nr : 0) * KDIM + kt + c4 * 8, ok ? 16u : 0u);
    }
    CP_COMMIT();
}

template <int AMODE, int EPI, int RELU>
__global__ __launch_bounds__(256, 1)
void gemm_mma(const __half* __restrict__ A, const __half* __restrict__ Wt,
              const float* __restrict__ bias, __half* __restrict__ Ch,
              float* __restrict__ incf,
              const int* __restrict__ esrc, const int* __restrict__ esnk,
              const __half* __restrict__ nsrc, const __half* __restrict__ incsrc,
              float* __restrict__ nsdst, __half* __restrict__ nstf,
              int M, int Ncol) {
    extern __shared__ __align__(16) char smem[];
    const uint32_t sb = smem_u32(smem);
    const int tid = threadIdx.x;
    const int wid = tid >> 5, lane = tid & 31;
    const int g = lane >> 2, t4 = lane & 3;
    const int wm = wid >> 2, wn = wid & 3;        // 2 x 4 warp grid
    const int m0 = blockIdx.y * TMv;
    const int n0 = blockIdx.x * TNv;
    const int bIdx = (AMODE == 1 || EPI == 1) ? (m0 / EE) : 0;
    int* sSrc = (int*)(smem + SOFF_SRC);
    int* sSnk = (int*)(smem + SOFF_SNK);

    if (AMODE == 1 || EPI == 1) {
        if (tid < TMv) {
            int e = (m0 - bIdx * EE) + tid;
            if (AMODE == 1) sSrc[tid] = esrc[e];
            sSnk[tid] = esnk[e];
        }
        __syncthreads();
    }

    // ldmatrix lane-constant address components (identical bytes to tf32 k8)
    const int sub = lane >> 3, r = lane & 7;
    const uint32_t aRowOff = (uint32_t)((wm * 64 + (sub & 1) * 8 + r) * 128);
    const uint32_t bRowOff = (uint32_t)((wn * 64 + (sub >> 1) * 8 + r) * 128);
    uint32_t aK[4], bK[4];
#pragma unroll
    for (int kk = 0; kk < 4; kk++) {
        aK[kk] = (uint32_t)((kk * 32 + (sub >> 1) * 16) ^ (r << 4));
        bK[kk] = (uint32_t)((kk * 32 + (sub & 1) * 16) ^ (r << 4));
    }

    float acc[4][8][4];
#pragma unroll
    for (int mt = 0; mt < 4; mt++)
#pragma unroll
        for (int nt = 0; nt < 8; nt++)
#pragma unroll
            for (int i = 0; i < 4; i++) acc[mt][nt][i] = 0.f;

    // Prologue: fill STAGES-1 buffers
#pragma unroll
    for (int c = 0; c < STAGES - 1; c++)
        load_chunk<AMODE>(c, sb, tid, m0, n0, bIdx, A, Wt, nsrc, incsrc, sSrc, sSnk, Ncol);

#pragma unroll 1
    for (int c = 0; c < NCHUNK; c++) {
        cp_wait<STAGES - 2>();
        __syncthreads();

        if (c + STAGES - 1 < NCHUNK)
            load_chunk<AMODE>(c + STAGES - 1, sb, tid, m0, n0, bIdx,
                              A, Wt, nsrc, incsrc, sSrc, sSnk, Ncol);

        const uint32_t abuf = sb + (uint32_t)(c & (STAGES - 1)) * BUFBYTES;
        const uint32_t bbuf = abuf + ABYTES_;
#pragma unroll
        for (int kk = 0; kk < 4; kk++) {          // k16 per kk
            uint32_t a[4][4];
#pragma unroll
            for (int mt = 0; mt < 4; mt++)
                LDSM4(a[mt][0], a[mt][1], a[mt][2], a[mt][3],
                      abuf + aRowOff + (uint32_t)(mt * 2048) + aK[kk]);
            uint32_t b[8][2];
#pragma unroll
            for (int p2 = 0; p2 < 4; p2++)
                LDSM4(b[2 * p2][0], b[2 * p2][1], b[2 * p2 + 1][0], b[2 * p2 + 1][1],
                      bbuf + bRowOff + (uint32_t)(p2 * 2048) + bK[kk]);
#pragma unroll
            for (int mt = 0; mt < 4; mt++)
#pragma unroll
                for (int nt = 0; nt < 8; nt++) mma16816(acc[mt][nt], a[mt], b[nt]);
        }
    }

    // Epilogue: thread owns rows {rl0, rl0+8} x cols {cc, cc+1} per (mt, nt)
#pragma unroll
    for (int mt = 0; mt < 4; mt++) {
        const int rl0 = wm * 64 + mt * 16 + g;
#pragma unroll
        for (int nt = 0; nt < 8; nt++) {
            const int cc = n0 + wn * 64 + nt * 8 + t4 * 2;
            const float b0v = bias[cc], b1v = bias[cc + 1];
            float v0 = acc[mt][nt][0] + b0v;
            float v1 = acc[mt][nt][1] + b1v;
            float v2 = acc[mt][nt][2] + b0v;
            float v3 = acc[mt][nt][3] + b1v;
            if (RELU) {
                v0 = fmaxf(v0, 0.f); v1 = fmaxf(v1, 0.f);
                v2 = fmaxf(v2, 0.f); v3 = fmaxf(v3, 0.f);
            }
            if (EPI == 0) {
                *(__half2*)(Ch + (size_t)(m0 + rl0) * Ncol + cc) = __floats2half2_rn(v0, v1);
                *(__half2*)(Ch + (size_t)(m0 + rl0 + 8) * Ncol + cc) = __floats2half2_rn(v2, v3);
            } else if (EPI == 1) {
                float* d0 = incf + ((size_t)bIdx * NN + sSnk[rl0]) * MSGD + cc;
                float* d1 = incf + ((size_t)bIdx * NN + sSnk[rl0 + 8]) * MSGD + cc;
                atomicAdd(d0, v0); atomicAdd(d0 + 1, v1);
                atomicAdd(d1, v2); atomicAdd(d1 + 1, v3);
            } else {
                size_t r0 = (size_t)(m0 + rl0) * DD + (DD - UPDD);
                size_t r1 = (size_t)(m0 + rl0 + 8) * DD + (DD - UPDD);
                if (cc < UPDD) {
                    float u0 = nsdst[r0 + cc] + v0; nsdst[r0 + cc] = u0; nstf[r0 + cc] = __float2half_rn(u0);
                    float u2 = nsdst[r1 + cc] + v2; nsdst[r1 + cc] = u2; nstf[r1 + cc] = __float2half_rn(u2);
                }
                if (cc + 1 < UPDD) {
                    float u1 = nsdst[r0 + cc + 1] + v1; nsdst[r0 + cc + 1] = u1; nstf[r0 + cc + 1] = __float2half_rn(u1);
                    float u3 = nsdst[r1 + cc + 1] + v3; nsdst[r1 + cc + 1] = u3; nstf[r1 + cc + 1] = __float2half_rn(u3);
                }
            }
        }
    }
}

// ---------------------------------------------------------------------------
// Glue kernels
// ---------------------------------------------------------------------------
__global__ void copy_round_kernel(float4* __restrict__ dst, __half2* __restrict__ dtf,
                                  const float4* __restrict__ src, int n4) {
    int i = blockIdx.x * blockDim.x + threadIdx.x;
    if (i >= n4) return;
    float4 v = src[i];
    dst[i] = v;
    dtf[i * 2]     = __floats2half2_rn(v.x, v.y);
    dtf[i * 2 + 1] = __floats2half2_rn(v.z, v.w);
}
__global__ void round4_kernel(__half2* __restrict__ dst, const float4* __restrict__ src, int n4) {
    int i = blockIdx.x * blockDim.x + threadIdx.x;
    if (i >= n4) return;
    float4 v = src[i];
    dst[i * 2]     = __floats2half2_rn(v.x, v.y);
    dst[i * 2 + 1] = __floats2half2_rn(v.z, v.w);
}
__global__ void zero4_kernel(float4* __restrict__ dst, int n4) {
    int i = blockIdx.x * blockDim.x + threadIdx.x;
    if (i < n4) dst[i] = make_float4(0.f, 0.f, 0.f, 0.f);
}
// out[n*K+k] = fp16(in[k*N+n])
__global__ void transpose_kernel(const float* __restrict__ in, __half* __restrict__ out,
                                 int K, int N) {
    __shared__ float t[32][33];
    int k0 = blockIdx.y * 32, n0 = blockIdx.x * 32;
    int tx = threadIdx.x, ty = threadIdx.y;
    for (int i = ty; i < 32; i += 8) {
        int k = k0 + i, n = n0 + tx;
        t[i][tx] = (k < K && n < N) ? in[(size_t)k * N + n] : 0.f;
    }
    __syncthreads();
    for (int i = ty; i < 32; i += 8) {
        int n = n0 + i, k = k0 + tx;
        if (n < N && k < K) out[(size_t)n * K + k] = __float2half_rn(t[tx][i]);
    }
}

// ---------------------------------------------------------------------------
// Extraction: out[b,p,d] += sum over n-chunk of attn[b,p,n] * ns[b,n,d]  (fp32)
// ---------------------------------------------------------------------------
__global__ __launch_bounds__(256)
void extract_kernel(const float* __restrict__ attn, const float* __restrict__ ns,
                    float* __restrict__ out) {
    const int b = blockIdx.z >> 5, kc = blockIdx.z & 31;
    const float* Ab = attn + (size_t)b * PP * NN + (size_t)kc * 128;
    const float* Bb = ns + (size_t)b * NN * DD + (size_t)kc * 128 * DD
                      + (size_t)blockIdx.x * 128;
    float* Cb = out + (size_t)b * PP * DD + (size_t)blockIdx.x * 128;

    __shared__ __align__(16) float sA[8][72];
    __shared__ __align__(16) float sB[8][132];
    const int tid = threadIdx.x;
    const int tx = tid & 15, ty = tid >> 4;

    float acc[4][8];
#pragma unroll
    for (int i = 0; i < 4; i++)
#pragma unroll
        for (int j = 0; j < 8; j++) acc[i][j] = 0.f;

    for (int kt = 0; kt < 128; kt += 8) {
        {
            int p = tid >> 2, kp = (tid & 3) * 2;
            float2 v = *(const float2*)(Ab + (size_t)p * NN + kt + kp);
            sA[kp][p] = v.x; sA[kp + 1][p] = v.y;
        }
        {
            int k = tid >> 5, d4 = (tid & 31) * 4;
            *(float4*)&sB[k][d4] = *(const float4*)(Bb + (size_t)(kt + k) * DD + d4);
        }
        __syncthreads();
#pragma unroll
        for (int kk = 0; kk < 8; kk++) {
            float a[4], bb[8];
#pragma unroll
            for (int i = 0; i < 4; i++) a[i] = sA[kk][ty * 4 + i];
#pragma unroll
            for (int j = 0; j < 8; j++) bb[j] = sB[kk][tx * 8 + j];
#pragma unroll
            for (int i = 0; i < 4; i++)
#pragma unroll
                for (int j = 0; j < 8; j++) acc[i][j] += a[i] * bb[j];
        }
        __syncthreads();
    }
#pragma unroll
    for (int i = 0; i < 4; i++) {
        int p = ty * 4 + i;
#pragma unroll
        for (int j = 0; j < 8; j++)
            atomicAdd(Cb + (size_t)p * DD + tx * 8 + j, acc[i][j]);
    }
}

// ---------------------------------------------------------------------------
// Launcher
// ---------------------------------------------------------------------------
extern "C" void kernel_launch(void* const* d_in, const int* in_sizes, int n_in,
                              void* d_out, int out_size) {
    (void)in_sizes; (void)n_in;
    const float* nodes = (const float*)d_in[0];
    const float* attn  = (const float*)d_in[1];
    const float* We1   = (const float*)d_in[2];
    const float* be1   = (const float*)d_in[3];
    const float* We2   = (const float*)d_in[4];
    const float* be2   = (const float*)d_in[5];
    const float* Wn1   = (const float*)d_in[6];
    const float* bn1   = (const float*)d_in[7];
    const float* Wn2   = (const float*)d_in[8];
    const float* bn2   = (const float*)d_in[9];
    const int*   esrc  = (const int*)d_in[10];
    const int*   esnk  = (const int*)d_in[11];
    float*       out   = (float*)d_out;

    float *ns, *inc;
    __half *nstf, *he, *inctf, *hn, *wte1, *wte2, *wtn1, *wtn2;
    cudaGetSymbolAddress((void**)&ns,    g_ns);
    cudaGetSymbolAddress((void**)&nstf,  g_nstf);
    cudaGetSymbolAddress((void**)&he,    g_he);
    cudaGetSymbolAddress((void**)&inc,   g_inc);
    cudaGetSymbolAddress((void**)&inctf, g_inctf);
    cudaGetSymbolAddress((void**)&hn,    g_hn);
    cudaGetSymbolAddress((void**)&wte1,  g_wte1);
    cudaGetSymbolAddress((void**)&wte2,  g_wte2);
    cudaGetSymbolAddress((void**)&wtn1,  g_wtn1);
    cudaGetSymbolAddress((void**)&wtn2,  g_wtn2);

    cudaFuncSetAttribute(gemm_mma<1, 0, 1>, cudaFuncAttributeMaxDynamicSharedMemorySize, SMEM_BYTES);
    cudaFuncSetAttribute(gemm_mma<0, 1, 0>, cudaFuncAttributeMaxDynamicSharedMemorySize, SMEM_BYTES);
    cudaFuncSetAttribute(gemm_mma<2, 0, 1>, cudaFuncAttributeMaxDynamicSharedMemorySize, SMEM_BYTES);
    cudaFuncSetAttribute(gemm_mma<0, 2, 0>, cudaFuncAttributeMaxDynamicSharedMemorySize, SMEM_BYTES);

    const int T = 256;
    const int ME = BB * EE;  // 131072
    const int MN = BB * NN;  // 32768
    const int nInc4 = BB * NN * MSGD / 4;

    // Order chosen so early app-launch indices land on GEMMs for ncu (-s 5).
    transpose_kernel<<<dim3(HH / 32, KDIM / 32), dim3(32, 8)>>>(We1, wte1, KDIM, HH);   // 0
    {
        int n4 = BB * NN * DD / 4;
        copy_round_kernel<<<(n4 + T - 1) / T, T>>>((float4*)ns, (__half2*)nstf,
                                                   (const float4*)nodes, n4);            // 1
    }
    zero4_kernel<<<(nInc4 + T - 1) / T, T>>>((float4*)inc, nInc4);                       // 2
    // GEMM1 step0                                                                        // 3
    gemm_mma<1, 0, 1><<<dim3(HH / TNv, ME / TMv), 256, SMEM_BYTES>>>(
        nullptr, wte1, be1, he, nullptr, esrc, esnk, nstf, nullptr, nullptr, nullptr, ME, HH);
    transpose_kernel<<<dim3(MSGD / 32, KDIM / 32), dim3(32, 8)>>>(We2, wte2, HH, MSGD);  // 4
    // GEMM2 step0                                                                        // 5
    gemm_mma<0, 1, 0><<<dim3(MSGD / TNv, ME / TMv), 256, SMEM_BYTES>>>(
        he, wte2, be2, nullptr, inc, esrc, esnk, nullptr, nullptr, nullptr, nullptr, ME, MSGD);
    transpose_kernel<<<dim3(HH / 32, KDIM / 32), dim3(32, 8)>>>(Wn1, wtn1, KDIM, HH);
    round4_kernel<<<(nInc4 + T - 1) / T, T>>>((__half2*)inctf, (const float4*)inc, nInc4);
    gemm_mma<2, 0, 1><<<dim3(HH / TNv, MN / TMv), 256, SMEM_BYTES>>>(
        nullptr, wtn1, bn1, hn, nullptr, nullptr, nullptr, nstf, inctf, nullptr, nullptr, MN, HH);
    transpose_kernel<<<dim3((UPDD + 31) / 32, KDIM / 32), dim3(32, 8)>>>(Wn2, wtn2, HH, UPDD);
    gemm_mma<0, 2, 0><<<dim3(1, MN / TMv), 256, SMEM_BYTES>>>(
        hn, wtn2, bn2, nullptr, nullptr, nullptr, nullptr, nullptr, nullptr, ns, nstf, MN, UPDD);

    for (int step = 1; step < STEPS; step++) {
        zero4_kernel<<<(nInc4 + T - 1) / T, T>>>((float4*)inc, nInc4);
        gemm_mma<1, 0, 1><<<dim3(HH / TNv, ME / TMv), 256, SMEM_BYTES>>>(
            nullptr, wte1, be1, he, nullptr, esrc, esnk, nstf, nullptr, nullptr, nullptr, ME, HH);
        gemm_mma<0, 1, 0><<<dim3(MSGD / TNv, ME / TMv), 256, SMEM_BYTES>>>(
            he, wte2, be2, nullptr, inc, esrc, esnk, nullptr, nullptr, nullptr, nullptr, ME, MSGD);
        round4_kernel<<<(nInc4 + T - 1) / T, T>>>((__half2*)inctf, (const float4*)inc, nInc4);
        gemm_mma<2, 0, 1><<<dim3(HH / TNv, MN / TMv), 256, SMEM_BYTES>>>(
            nullptr, wtn1, bn1, hn, nullptr, nullptr, nullptr, nstf, inctf, nullptr, nullptr, MN, HH);
        gemm_mma<0, 2, 0><<<dim3(1, MN / TMv), 256, SMEM_BYTES>>>(
            hn, wtn2, bn2, nullptr, nullptr, nullptr, nullptr, nullptr, nullptr, ns, nstf, MN, UPDD);
    }

    // extraction: out[b,p,d] = sum_n attn[b,p,n] * ns[b,n,d]  (fp32, split-K + atomics)
    {
        int n4 = BB * PP * DD / 4;
        zero4_kernel<<<(n4 + T - 1) / T, T>>>((float4*)out, n4);
        extract_kernel<<<dim3(DD / 128, 1, BB * 32), 256>>>(attn, ns, out);
    }
}